// round 4
// baseline (speedup 1.0000x reference)
#include <cuda_runtime.h>
#include <mma.h>
#include <cstdint>

using namespace nvcuda;

#define N_NODES  100000
#define N_EDGES  1600000
#define HID      96
#define N_GRAPHS 2048

// ---------------- scratch (device globals; no allocation allowed) ----------
__device__ int   g_deg[N_NODES];
__device__ int   g_rowptr[N_NODES + 1];
__device__ int   g_cursor[N_NODES];
__device__ int   g_col[N_EDGES];
__device__ float g_dinv[N_NODES];
__device__ float g_bufA[N_NODES * HID];
__device__ float g_bufB[N_NODES * HID];
__device__ float g_pool[N_GRAPHS * HID];

__device__ __forceinline__ float to_tf32(float x) {
    float r;
    asm("cvt.rna.tf32.f32 %0, %1;" : "=f"(r) : "f"(x));
    return r;
}

// ---------------- CSR build ------------------------------------------------
__global__ __launch_bounds__(256) void zero_deg_kernel() {
    int i = blockIdx.x * blockDim.x + threadIdx.x;
    if (i < N_NODES) g_deg[i] = 0;
}

__global__ __launch_bounds__(256) void count_kernel(const int* __restrict__ ei) {
    int e = blockIdx.x * blockDim.x + threadIdx.x;
    if (e < N_EDGES) atomicAdd(&g_deg[ei[N_EDGES + e]], 1);
}

__global__ __launch_bounds__(1024) void scan_kernel() {
    __shared__ int part[1024];
    const int C = (N_NODES + 1023) / 1024;
    int t = threadIdx.x;
    int s = 0;
    for (int j = 0; j < C; j++) {
        int idx = t * C + j;
        if (idx < N_NODES) s += g_deg[idx];
    }
    part[t] = s;
    __syncthreads();
    for (int off = 1; off < 1024; off <<= 1) {
        int v = (t >= off) ? part[t - off] : 0;
        __syncthreads();
        part[t] += v;
        __syncthreads();
    }
    int run = (t == 0) ? 0 : part[t - 1];
    for (int j = 0; j < C; j++) {
        int idx = t * C + j;
        if (idx < N_NODES) {
            g_rowptr[idx] = run;
            run += g_deg[idx];
        }
    }
    if (t == 1023) g_rowptr[N_NODES] = run;
}

__global__ __launch_bounds__(256) void dinv_cursor_kernel() {
    int i = blockIdx.x * blockDim.x + threadIdx.x;
    if (i < N_NODES) {
        g_dinv[i]   = rsqrtf((float)(g_deg[i] + 1));
        g_cursor[i] = g_rowptr[i];
    }
}

__global__ __launch_bounds__(256) void fill_kernel(const int* __restrict__ ei) {
    int e = blockIdx.x * blockDim.x + threadIdx.x;
    if (e < N_EDGES) {
        int s = ei[e];
        int d = ei[N_EDGES + e];
        int pos = atomicAdd(&g_cursor[d], 1);
        g_col[pos] = s;
    }
}

// ---------------- xs0 = x * dinv -------------------------------------------
__global__ __launch_bounds__(256) void scale0_kernel(const float* __restrict__ x) {
    int idx = blockIdx.x * blockDim.x + threadIdx.x;
    if (idx < N_NODES * 8) {
        int node = idx >> 3;
        float d = g_dinv[node];
        float4 v = ((const float4*)x)[idx];
        v.x *= d; v.y *= d; v.z *= d; v.w *= d;
        ((float4*)g_bufA)[idx] = v;
    }
}

// ---------------- aggregation ----------------------------------------------
template <int F4>
__global__ __launch_bounds__(256) void agg_kernel(const float* __restrict__ xs,
                                                  float* __restrict__ out) {
    int gtid = blockIdx.x * blockDim.x + threadIdx.x;
    int warp = gtid >> 5;
    int lane = threadIdx.x & 31;
    int node, f;
    if (F4 == 8) { node = warp * 4 + (lane >> 3); f = lane & 7; }
    else         { node = warp; f = lane; if (f >= F4) return; }
    if (node >= N_NODES) return;

    const float4* x4 = (const float4*)xs;
    float4 acc = x4[(long)node * F4 + f];
    int e0 = g_rowptr[node];
    int e1 = g_rowptr[node + 1];
    for (int e = e0; e < e1; e++) {
        int s = g_col[e];
        float4 v = __ldg(&x4[(long)s * F4 + f]);
        acc.x += v.x; acc.y += v.y; acc.z += v.z; acc.w += v.w;
    }
    float d = g_dinv[node];
    acc.x *= d; acc.y *= d; acc.z *= d; acc.w *= d;
    ((float4*)out)[(long)node * F4 + f] = acc;
}

// ---------------- wmma tf32 GEMM -------------------------------------------
// C[row0..row0+127, 0..95] = act( A[128,KD] @ W[KD,96] + b ) (* dinv)
// 128 threads = 4 warps; warp tile 64 rows x 48 cols (4x3 wmma 16x16 frags).
template <int KD, bool SCALE>
__global__ __launch_bounds__(128) void gemm_wmma(const float* __restrict__ A,
                                                 float* __restrict__ C,
                                                 const float* __restrict__ W,
                                                 const float* __restrict__ b) {
    extern __shared__ float sh[];
    const int KP   = KD + 8;                       // padded A stride
    const int OFFW = 128 * KP;                     // sW offset
    const int AW   = 128 * KP + KD * 96;
    const int OFFB = (AW > 128 * 96) ? AW : 128 * 96;  // bias beyond C region

    float* sA = sh;
    float* sW = sh + OFFW;
    float* sB = sh + OFFB;

    int tid = threadIdx.x, wid = tid >> 5;
    int row0 = blockIdx.x * 128;

    // stage W (tf32) + bias
    for (int i = tid; i < KD * 96; i += 128) sW[i] = to_tf32(W[i]);
    if (tid < 96) sB[tid] = b[tid];

    // stage A (tf32), zero-fill tail rows
    for (int i = tid; i < 128 * (KD / 4); i += 128) {
        int r  = i / (KD / 4);
        int c4 = i % (KD / 4);
        int gr = row0 + r;
        float4 v = make_float4(0.f, 0.f, 0.f, 0.f);
        if (gr < N_NODES) v = ((const float4*)A)[(long)gr * (KD / 4) + c4];
        float* p = &sA[r * KP + c4 * 4];
        p[0] = to_tf32(v.x); p[1] = to_tf32(v.y);
        p[2] = to_tf32(v.z); p[3] = to_tf32(v.w);
    }
    __syncthreads();

    const int wm = (wid >> 1) * 64;   // warp row offset: 0 or 64
    const int wn = (wid & 1) * 48;    // warp col offset: 0 or 48

    wmma::fragment<wmma::accumulator, 16, 16, 8, float> acc[4][3];
#pragma unroll
    for (int i = 0; i < 4; i++)
#pragma unroll
        for (int j = 0; j < 3; j++) wmma::fill_fragment(acc[i][j], 0.f);

#pragma unroll
    for (int k0 = 0; k0 < KD; k0 += 8) {
        wmma::fragment<wmma::matrix_a, 16, 16, 8, wmma::precision::tf32, wmma::row_major> af[4];
        wmma::fragment<wmma::matrix_b, 16, 16, 8, wmma::precision::tf32, wmma::row_major> bf[3];
#pragma unroll
        for (int i = 0; i < 4; i++)
            wmma::load_matrix_sync(af[i], &sA[(wm + i * 16) * KP + k0], KP);
#pragma unroll
        for (int j = 0; j < 3; j++)
            wmma::load_matrix_sync(bf[j], &sW[k0 * 96 + wn + j * 16], 96);
#pragma unroll
        for (int i = 0; i < 4; i++)
#pragma unroll
            for (int j = 0; j < 3; j++)
                wmma::mma_sync(acc[i][j], af[i], bf[j], acc[i][j]);
    }

    __syncthreads();   // done reading sA/sW; reuse as C staging
    float* sC = sh;
#pragma unroll
    for (int i = 0; i < 4; i++)
#pragma unroll
        for (int j = 0; j < 3; j++)
            wmma::store_matrix_sync(&sC[(wm + i * 16) * 96 + wn + j * 16],
                                    acc[i][j], 96, wmma::mem_row_major);
    __syncthreads();

    // fused epilogue: bias + relu (+ dinv), coalesced float4 stores
    for (int i = tid; i < 128 * 24; i += 128) {
        int r = i / 24, c4 = i % 24;
        int row = row0 + r;
        if (row >= N_NODES) continue;
        float d = SCALE ? g_dinv[row] : 1.f;
        float4 v = ((const float4*)sC)[r * 24 + c4];
        int c = c4 * 4;
        v.x = fmaxf(v.x + sB[c + 0], 0.f) * d;
        v.y = fmaxf(v.y + sB[c + 1], 0.f) * d;
        v.z = fmaxf(v.z + sB[c + 2], 0.f) * d;
        v.w = fmaxf(v.w + sB[c + 3], 0.f) * d;
        ((float4*)&C[(long)row * 96])[c4] = v;
    }
}

// ---------------- global add pool ------------------------------------------
__global__ __launch_bounds__(256) void zero_pool_kernel() {
    int i = blockIdx.x * blockDim.x + threadIdx.x;
    if (i < N_GRAPHS * HID / 4) ((float4*)g_pool)[i] = make_float4(0.f, 0.f, 0.f, 0.f);
}

__global__ __launch_bounds__(256) void pool_kernel(const int* __restrict__ batch,
                                                   const float* __restrict__ h) {
    const int CH = 128;
    int warp = (blockIdx.x * blockDim.x + threadIdx.x) >> 5;
    int lane = threadIdx.x & 31;
    if (lane >= 24) return;
    int n0 = warp * CH;
    if (n0 >= N_NODES) return;
    int n1 = min(n0 + CH, N_NODES);

    const float4* h4 = (const float4*)h;
    int cur = batch[n0];
    float4 acc = make_float4(0.f, 0.f, 0.f, 0.f);
    for (int n = n0; n < n1; n++) {
        int bg = batch[n];
        if (bg != cur) {
            float* p = &g_pool[cur * HID + lane * 4];
            atomicAdd(p + 0, acc.x); atomicAdd(p + 1, acc.y);
            atomicAdd(p + 2, acc.z); atomicAdd(p + 3, acc.w);
            acc = make_float4(0.f, 0.f, 0.f, 0.f);
            cur = bg;
        }
        float4 v = h4[(long)n * 24 + lane];
        acc.x += v.x; acc.y += v.y; acc.z += v.z; acc.w += v.w;
    }
    float* p = &g_pool[cur * HID + lane * 4];
    atomicAdd(p + 0, acc.x); atomicAdd(p + 1, acc.y);
    atomicAdd(p + 2, acc.z); atomicAdd(p + 3, acc.w);
}

// ---------------- final MLP ------------------------------------------------
__global__ __launch_bounds__(128) void mlp_kernel(const float* __restrict__ Wf1,
                                                  const float* __restrict__ bf1,
                                                  const float* __restrict__ Wf2,
                                                  const float* __restrict__ bf2,
                                                  float* __restrict__ out) {
    int g = blockIdx.x * 4 + (threadIdx.x >> 5);
    int j = threadIdx.x & 31;
    if (g >= N_GRAPHS) return;
    float hj = bf1[j];
    const float* gp = &g_pool[g * HID];
#pragma unroll 8
    for (int i = 0; i < 96; i++) hj += gp[i] * Wf1[i * 32 + j];
    hj = fmaxf(hj, 0.f);
    float v = hj * Wf2[j];
#pragma unroll
    for (int off = 16; off; off >>= 1) v += __shfl_down_sync(0xffffffffu, v, off);
    if (j == 0) out[g] = v + bf2[0];
}

// ---------------- launch ---------------------------------------------------
extern "C" void kernel_launch(void* const* d_in, const int* in_sizes, int n_in,
                              void* d_out, int out_size) {
    const float* x     = (const float*)d_in[0];
    const int*   ei    = (const int*)d_in[1];
    const int*   batch = (const int*)d_in[2];
    const float* W1  = (const float*)d_in[3];
    const float* b1  = (const float*)d_in[4];
    const float* W2  = (const float*)d_in[5];
    const float* b2  = (const float*)d_in[6];
    const float* W3  = (const float*)d_in[7];
    const float* b3  = (const float*)d_in[8];
    const float* W4  = (const float*)d_in[9];
    const float* b4  = (const float*)d_in[10];
    const float* Wf1 = (const float*)d_in[11];
    const float* bf1 = (const float*)d_in[12];
    const float* Wf2 = (const float*)d_in[13];
    const float* bf2 = (const float*)d_in[14];
    float* out = (float*)d_out;

    float *bufA, *bufB;
    cudaGetSymbolAddress((void**)&bufA, g_bufA);
    cudaGetSymbolAddress((void**)&bufB, g_bufB);

    // dynamic smem sizes (floats -> bytes)
    const int AW96 = 128 * (96 + 8) + 96 * 96;               // 22528
    const int SM96 = (AW96 + 96) * 4;                        // 90496 B
    const int AW32 = 128 * (32 + 8) + 32 * 96;               // 8192
    const int SM32 = ((AW32 > 128 * 96 ? AW32 : 128 * 96) + 96) * 4;  // 49536 B
    cudaFuncSetAttribute(gemm_wmma<96, true>,  cudaFuncAttributeMaxDynamicSharedMemorySize, SM96);
    cudaFuncSetAttribute(gemm_wmma<96, false>, cudaFuncAttributeMaxDynamicSharedMemorySize, SM96);
    cudaFuncSetAttribute(gemm_wmma<32, true>,  cudaFuncAttributeMaxDynamicSharedMemorySize, SM32);

    const int TB = 256;
    int nb_nodes = (N_NODES + TB - 1) / TB;
    int nb_edges = (N_EDGES + TB - 1) / TB;

    // CSR build
    zero_deg_kernel<<<nb_nodes, TB>>>();
    count_kernel<<<nb_edges, TB>>>(ei);
    scan_kernel<<<1, 1024>>>();
    dinv_cursor_kernel<<<nb_nodes, TB>>>();
    fill_kernel<<<nb_edges, TB>>>(ei);

    // xs0 = x * dinv
    scale0_kernel<<<(N_NODES * 8 + TB - 1) / TB, TB>>>(x);

    const int AGG8_BLKS  = (N_NODES / 4 * 32 + TB - 1) / TB;
    const int AGG24_BLKS = ((long)N_NODES * 32 + TB - 1) / TB;
    const int GEMM_BLKS  = (N_NODES + 127) / 128;   // 782

    // layer 1
    agg_kernel<8><<<AGG8_BLKS, TB>>>(bufA, bufB);
    gemm_wmma<32, true><<<GEMM_BLKS, 128, SM32>>>(bufB, bufA, W1, b1);
    // layer 2
    agg_kernel<24><<<AGG24_BLKS, TB>>>(bufA, bufB);
    gemm_wmma<96, true><<<GEMM_BLKS, 128, SM96>>>(bufB, bufA, W2, b2);
    // layer 3
    agg_kernel<24><<<AGG24_BLKS, TB>>>(bufA, bufB);
    gemm_wmma<96, true><<<GEMM_BLKS, 128, SM96>>>(bufB, bufA, W3, b3);
    // layer 4
    agg_kernel<24><<<AGG24_BLKS, TB>>>(bufA, bufB);
    gemm_wmma<96, false><<<GEMM_BLKS, 128, SM96>>>(bufB, bufA, W4, b4);

    // pool + MLP
    zero_pool_kernel<<<(N_GRAPHS * HID / 4 + TB - 1) / TB, TB>>>();
    int pool_warps = (N_NODES + 127) / 128;
    pool_kernel<<<(pool_warps * 32 + TB - 1) / TB, TB>>>(batch, bufA);
    mlp_kernel<<<N_GRAPHS / 4, 128>>>(Wf1, bf1, Wf2, bf2, out);
}

// round 5
// speedup vs baseline: 1.1540x; 1.1540x over previous
#include <cuda_runtime.h>
#include <cuda_fp16.h>
#include <mma.h>
#include <cstdint>

using namespace nvcuda;

#define N_NODES  100000
#define N_EDGES  1600000
#define HID      96
#define N_GRAPHS 2048

// ---------------- scratch (device globals; no allocation allowed) ----------
__device__ int    g_deg[N_NODES];
__device__ int    g_rowptr[N_NODES + 1];
__device__ int    g_cursor[N_NODES];
__device__ int    g_col[N_EDGES];
__device__ float  g_dinv[N_NODES];
__device__ __half g_bufA[N_NODES * HID];
__device__ __half g_bufB[N_NODES * HID];
__device__ float  g_pool[N_GRAPHS * HID];

// ---------------- half4 helpers --------------------------------------------
__device__ __forceinline__ float4 h4_to_f4(uint2 u) {
    __half2 a = *reinterpret_cast<__half2*>(&u.x);
    __half2 b = *reinterpret_cast<__half2*>(&u.y);
    float2 fa = __half22float2(a), fb = __half22float2(b);
    return make_float4(fa.x, fa.y, fb.x, fb.y);
}
__device__ __forceinline__ uint2 f4_to_h4(float4 v) {
    __half2 a = __floats2half2_rn(v.x, v.y);
    __half2 b = __floats2half2_rn(v.z, v.w);
    uint2 u;
    u.x = *reinterpret_cast<uint32_t*>(&a);
    u.y = *reinterpret_cast<uint32_t*>(&b);
    return u;
}

// ---------------- CSR build ------------------------------------------------
__global__ __launch_bounds__(256) void zero_deg_kernel() {
    int i = blockIdx.x * blockDim.x + threadIdx.x;
    if (i < N_NODES) g_deg[i] = 0;
}

__global__ __launch_bounds__(256) void count_kernel(const int* __restrict__ ei) {
    int e = blockIdx.x * blockDim.x + threadIdx.x;
    if (e < N_EDGES) atomicAdd(&g_deg[ei[N_EDGES + e]], 1);
}

// scan + dinv + cursor fused (single block, 1024 threads)
__global__ __launch_bounds__(1024) void scan_kernel() {
    __shared__ int part[1024];
    const int C = (N_NODES + 1023) / 1024;
    int t = threadIdx.x;
    int s = 0;
    for (int j = 0; j < C; j++) {
        int idx = t * C + j;
        if (idx < N_NODES) s += g_deg[idx];
    }
    part[t] = s;
    __syncthreads();
    for (int off = 1; off < 1024; off <<= 1) {
        int v = (t >= off) ? part[t - off] : 0;
        __syncthreads();
        part[t] += v;
        __syncthreads();
    }
    int run = (t == 0) ? 0 : part[t - 1];
    for (int j = 0; j < C; j++) {
        int idx = t * C + j;
        if (idx < N_NODES) {
            int d = g_deg[idx];
            g_rowptr[idx] = run;
            g_cursor[idx] = run;
            g_dinv[idx]   = rsqrtf((float)(d + 1));
            run += d;
        }
    }
    if (t == 1023) g_rowptr[N_NODES] = run;
}

__global__ __launch_bounds__(256) void fill_kernel(const int* __restrict__ ei) {
    int e = blockIdx.x * blockDim.x + threadIdx.x;
    if (e < N_EDGES) {
        int s = ei[e];
        int d = ei[N_EDGES + e];
        int pos = atomicAdd(&g_cursor[d], 1);
        g_col[pos] = s;
    }
}

// ---------------- xs0 = half(x * dinv)  [N,32] ------------------------------
__global__ __launch_bounds__(256) void scale0_kernel(const float* __restrict__ x,
                                                     __half* __restrict__ out) {
    int idx = blockIdx.x * blockDim.x + threadIdx.x;   // float4 / uint2 index
    if (idx < N_NODES * 8) {
        int node = idx >> 3;
        float d = g_dinv[node];
        float4 v = ((const float4*)x)[idx];
        v.x *= d; v.y *= d; v.z *= d; v.w *= d;
        ((uint2*)out)[idx] = f4_to_h4(v);
    }
}

// ---------------- aggregation (fp16 in, fp32 acc, fp16 out) ----------------
// U2 = uint2 (4 halves) per node row.  U2==8: 4 nodes/warp.  U2==24: 1 node/warp.
template <int U2>
__global__ __launch_bounds__(256) void agg_kernel(const __half* __restrict__ xs,
                                                  __half* __restrict__ out) {
    int gtid = blockIdx.x * blockDim.x + threadIdx.x;
    int warp = gtid >> 5;
    int lane = threadIdx.x & 31;
    int node, f;
    if (U2 == 8) { node = warp * 4 + (lane >> 3); f = lane & 7; }
    else         { node = warp; f = lane; if (f >= U2) return; }
    if (node >= N_NODES) return;

    const uint2* x2 = (const uint2*)xs;
    float4 acc = h4_to_f4(x2[(long)node * U2 + f]);   // self term
    int e0 = g_rowptr[node];
    int e1 = g_rowptr[node + 1];
    for (int e = e0; e < e1; e++) {
        int s = g_col[e];
        float4 v = h4_to_f4(__ldg(&x2[(long)s * U2 + f]));
        acc.x += v.x; acc.y += v.y; acc.z += v.z; acc.w += v.w;
    }
    float d = g_dinv[node];
    acc.x *= d; acc.y *= d; acc.z *= d; acc.w *= d;
    ((uint2*)out)[(long)node * U2 + f] = f4_to_h4(acc);
}

// ---------------- wmma fp16 GEMM -------------------------------------------
// C[row0..row0+127, 0..95] = half( act( A[128,KD] @ W[KD,96] + b ) (* dinv) )
// 256 threads = 8 warps; warp tile 32 rows x 48 cols (2x3 m16n16k16 frags).
template <int KD, bool SCALE>
__global__ __launch_bounds__(256) void gemm_wmma(const __half* __restrict__ A,
                                                 __half* __restrict__ C,
                                                 const float* __restrict__ W,
                                                 const float* __restrict__ b) {
    extern __shared__ __align__(16) char smem[];
    const int KP = KD + 8;                       // padded A stride (halves)
    __half* sA = (__half*)smem;                  // 128 * KP halves
    __half* sW = (__half*)(smem + 128 * KP * 2); // KD * 96 halves
    float*  sC = (float*)smem;                   // reused: 128 * 96 floats
    float*  sB = (float*)(smem + 128 * 96 * 4);  // 96 floats

    int tid = threadIdx.x, wid = tid >> 5;
    int row0 = blockIdx.x * 128;

    // stage W -> half
    for (int i = tid; i < KD * 96; i += 256) sW[i] = __float2half(W[i]);
    if (tid < 96) sB[tid] = b[tid];

    // stage A (already half): uint4 copies, zero-fill tail rows
    const int RU4 = KD / 8;                      // uint4 per row
    for (int i = tid; i < 128 * RU4; i += 256) {
        int r = i / RU4, c = i % RU4;
        int gr = row0 + r;
        uint4 v = make_uint4(0u, 0u, 0u, 0u);
        if (gr < N_NODES) v = ((const uint4*)A)[(long)gr * RU4 + c];
        *(uint4*)&sA[r * KP + c * 8] = v;
    }
    __syncthreads();

    const int wm = (wid >> 1) * 32;   // warp row offset: 0/32/64/96
    const int wn = (wid & 1) * 48;    // warp col offset: 0/48

    wmma::fragment<wmma::accumulator, 16, 16, 16, float> acc[2][3];
#pragma unroll
    for (int i = 0; i < 2; i++)
#pragma unroll
        for (int j = 0; j < 3; j++) wmma::fill_fragment(acc[i][j], 0.f);

#pragma unroll
    for (int k0 = 0; k0 < KD; k0 += 16) {
        wmma::fragment<wmma::matrix_a, 16, 16, 16, __half, wmma::row_major> af[2];
        wmma::fragment<wmma::matrix_b, 16, 16, 16, __half, wmma::row_major> bf[3];
#pragma unroll
        for (int i = 0; i < 2; i++)
            wmma::load_matrix_sync(af[i], &sA[(wm + i * 16) * KP + k0], KP);
#pragma unroll
        for (int j = 0; j < 3; j++)
            wmma::load_matrix_sync(bf[j], &sW[k0 * 96 + wn + j * 16], 96);
#pragma unroll
        for (int i = 0; i < 2; i++)
#pragma unroll
            for (int j = 0; j < 3; j++)
                wmma::mma_sync(acc[i][j], af[i], bf[j], acc[i][j]);
    }

    __syncthreads();   // done reading sA/sW; reuse as C staging
#pragma unroll
    for (int i = 0; i < 2; i++)
#pragma unroll
        for (int j = 0; j < 3; j++)
            wmma::store_matrix_sync(&sC[(wm + i * 16) * 96 + wn + j * 16],
                                    acc[i][j], 96, wmma::mem_row_major);
    __syncthreads();

    // fused epilogue: bias + relu (+ dinv) -> half, coalesced uint2 stores
    for (int i = tid; i < 128 * 24; i += 256) {
        int r = i / 24, c2 = i % 24;
        int row = row0 + r;
        if (row >= N_NODES) continue;
        float d = SCALE ? g_dinv[row] : 1.f;
        const float* p = &sC[r * 96 + c2 * 4];
        float4 v;
        int c = c2 * 4;
        v.x = fmaxf(p[0] + sB[c + 0], 0.f) * d;
        v.y = fmaxf(p[1] + sB[c + 1], 0.f) * d;
        v.z = fmaxf(p[2] + sB[c + 2], 0.f) * d;
        v.w = fmaxf(p[3] + sB[c + 3], 0.f) * d;
        ((uint2*)&C[(long)row * 96])[c2] = f4_to_h4(v);
    }
}

// ---------------- global add pool ------------------------------------------
__global__ __launch_bounds__(256) void zero_pool_kernel() {
    int i = blockIdx.x * blockDim.x + threadIdx.x;
    if (i < N_GRAPHS * HID / 4) ((float4*)g_pool)[i] = make_float4(0.f, 0.f, 0.f, 0.f);
}

__global__ __launch_bounds__(256) void pool_kernel(const int* __restrict__ batch,
                                                   const __half* __restrict__ h) {
    const int CH = 128;
    int warp = (blockIdx.x * blockDim.x + threadIdx.x) >> 5;
    int lane = threadIdx.x & 31;
    if (lane >= 24) return;
    int n0 = warp * CH;
    if (n0 >= N_NODES) return;
    int n1 = min(n0 + CH, N_NODES);

    const uint2* h2 = (const uint2*)h;
    int cur = batch[n0];
    float4 acc = make_float4(0.f, 0.f, 0.f, 0.f);
    for (int n = n0; n < n1; n++) {
        int bg = batch[n];
        if (bg != cur) {
            float* p = &g_pool[cur * HID + lane * 4];
            atomicAdd(p + 0, acc.x); atomicAdd(p + 1, acc.y);
            atomicAdd(p + 2, acc.z); atomicAdd(p + 3, acc.w);
            acc = make_float4(0.f, 0.f, 0.f, 0.f);
            cur = bg;
        }
        float4 v = h4_to_f4(h2[(long)n * 24 + lane]);
        acc.x += v.x; acc.y += v.y; acc.z += v.z; acc.w += v.w;
    }
    float* p = &g_pool[cur * HID + lane * 4];
    atomicAdd(p + 0, acc.x); atomicAdd(p + 1, acc.y);
    atomicAdd(p + 2, acc.z); atomicAdd(p + 3, acc.w);
}

// ---------------- final MLP ------------------------------------------------
__global__ __launch_bounds__(128) void mlp_kernel(const float* __restrict__ Wf1,
                                                  const float* __restrict__ bf1,
                                                  const float* __restrict__ Wf2,
                                                  const float* __restrict__ bf2,
                                                  float* __restrict__ out) {
    int g = blockIdx.x * 4 + (threadIdx.x >> 5);
    int j = threadIdx.x & 31;
    if (g >= N_GRAPHS) return;
    float hj = bf1[j];
    const float* gp = &g_pool[g * HID];
#pragma unroll 8
    for (int i = 0; i < 96; i++) hj += gp[i] * Wf1[i * 32 + j];
    hj = fmaxf(hj, 0.f);
    float v = hj * Wf2[j];
#pragma unroll
    for (int off = 16; off; off >>= 1) v += __shfl_down_sync(0xffffffffu, v, off);
    if (j == 0) out[g] = v + bf2[0];
}

// ---------------- launch ---------------------------------------------------
extern "C" void kernel_launch(void* const* d_in, const int* in_sizes, int n_in,
                              void* d_out, int out_size) {
    const float* x     = (const float*)d_in[0];
    const int*   ei    = (const int*)d_in[1];
    const int*   batch = (const int*)d_in[2];
    const float* W1  = (const float*)d_in[3];
    const float* b1  = (const float*)d_in[4];
    const float* W2  = (const float*)d_in[5];
    const float* b2  = (const float*)d_in[6];
    const float* W3  = (const float*)d_in[7];
    const float* b3  = (const float*)d_in[8];
    const float* W4  = (const float*)d_in[9];
    const float* b4  = (const float*)d_in[10];
    const float* Wf1 = (const float*)d_in[11];
    const float* bf1 = (const float*)d_in[12];
    const float* Wf2 = (const float*)d_in[13];
    const float* bf2 = (const float*)d_in[14];
    float* out = (float*)d_out;

    __half *bufA, *bufB;
    cudaGetSymbolAddress((void**)&bufA, g_bufA);
    cudaGetSymbolAddress((void**)&bufB, g_bufB);

    // dynamic smem: C staging (128*96 fp32) + bias; staging A/W fits inside
    const int SM = 128 * 96 * 4 + 96 * 4;   // 49536 B
    cudaFuncSetAttribute(gemm_wmma<96, true>,  cudaFuncAttributeMaxDynamicSharedMemorySize, SM);
    cudaFuncSetAttribute(gemm_wmma<96, false>, cudaFuncAttributeMaxDynamicSharedMemorySize, SM);
    cudaFuncSetAttribute(gemm_wmma<32, true>,  cudaFuncAttributeMaxDynamicSharedMemorySize, SM);

    const int TB = 256;
    int nb_nodes = (N_NODES + TB - 1) / TB;
    int nb_edges = (N_EDGES + TB - 1) / TB;

    // CSR build
    zero_deg_kernel<<<nb_nodes, TB>>>();
    count_kernel<<<nb_edges, TB>>>(ei);
    scan_kernel<<<1, 1024>>>();
    fill_kernel<<<nb_edges, TB>>>(ei);

    // xs0 = half(x * dinv)
    scale0_kernel<<<(N_NODES * 8 + TB - 1) / TB, TB>>>(x, bufA);

    const int AGG8_BLKS  = (N_NODES / 4 * 32 + TB - 1) / TB;
    const int AGG24_BLKS = ((long)N_NODES * 32 + TB - 1) / TB;
    const int GEMM_BLKS  = (N_NODES + 127) / 128;   // 782

    // layer 1
    agg_kernel<8><<<AGG8_BLKS, TB>>>(bufA, bufB);
    gemm_wmma<32, true><<<GEMM_BLKS, 256, SM>>>(bufB, bufA, W1, b1);
    // layer 2
    agg_kernel<24><<<AGG24_BLKS, TB>>>(bufA, bufB);
    gemm_wmma<96, true><<<GEMM_BLKS, 256, SM>>>(bufB, bufA, W2, b2);
    // layer 3
    agg_kernel<24><<<AGG24_BLKS, TB>>>(bufA, bufB);
    gemm_wmma<96, true><<<GEMM_BLKS, 256, SM>>>(bufB, bufA, W3, b3);
    // layer 4
    agg_kernel<24><<<AGG24_BLKS, TB>>>(bufA, bufB);
    gemm_wmma<96, false><<<GEMM_BLKS, 256, SM>>>(bufB, bufA, W4, b4);

    // pool + MLP
    zero_pool_kernel<<<(N_GRAPHS * HID / 4 + TB - 1) / TB, TB>>>();
    int pool_warps = (N_NODES + 127) / 128;
    pool_kernel<<<(pool_warps * 32 + TB - 1) / TB, TB>>>(batch, bufA);
    mlp_kernel<<<N_GRAPHS / 4, 128>>>(Wf1, bf1, Wf2, bf2, out);
}

// round 6
// speedup vs baseline: 1.1851x; 1.0270x over previous
#include <cuda_runtime.h>
#include <cuda_fp16.h>
#include <mma.h>
#include <cstdint>

using namespace nvcuda;

#define N_NODES  100000
#define N_EDGES  1600000
#define HID      96
#define N_GRAPHS 2048

// ---------------- scratch (device globals; no allocation allowed) ----------
__device__ int    g_deg[N_NODES];
__device__ int    g_rowptr[N_NODES + 1];
__device__ int    g_cursor[N_NODES];
__device__ int    g_col[N_EDGES];
__device__ float  g_dinv[N_NODES];
__device__ __half g_bufA[N_NODES * HID];
__device__ __half g_bufB[N_NODES * HID];
__device__ float  g_pool[N_GRAPHS * HID];
__device__ __half g_wh[3072 + 3 * 9216];   // W1(32x96), W2,W3,W4(96x96) in fp16

// ---------------- half4 helpers --------------------------------------------
__device__ __forceinline__ float4 h4_to_f4(uint2 u) {
    __half2 a = *reinterpret_cast<__half2*>(&u.x);
    __half2 b = *reinterpret_cast<__half2*>(&u.y);
    float2 fa = __half22float2(a), fb = __half22float2(b);
    return make_float4(fa.x, fa.y, fb.x, fb.y);
}
__device__ __forceinline__ uint2 f4_to_h4(float4 v) {
    __half2 a = __floats2half2_rn(v.x, v.y);
    __half2 b = __floats2half2_rn(v.z, v.w);
    uint2 u;
    u.x = *reinterpret_cast<uint32_t*>(&a);
    u.y = *reinterpret_cast<uint32_t*>(&b);
    return u;
}

// ---------------- CSR build ------------------------------------------------
__global__ __launch_bounds__(256) void zero_deg_kernel() {
    int i = blockIdx.x * blockDim.x + threadIdx.x;
    if (i < N_NODES) g_deg[i] = 0;
}

__global__ __launch_bounds__(256) void count_kernel(const int* __restrict__ ei) {
    int e = blockIdx.x * blockDim.x + threadIdx.x;
    if (e < N_EDGES) atomicAdd(&g_deg[ei[N_EDGES + e]], 1);
}

// scan + dinv + cursor fused (single block, 1024 threads)
__global__ __launch_bounds__(1024) void scan_kernel() {
    __shared__ int part[1024];
    const int C = (N_NODES + 1023) / 1024;
    int t = threadIdx.x;
    int s = 0;
    for (int j = 0; j < C; j++) {
        int idx = t * C + j;
        if (idx < N_NODES) s += g_deg[idx];
    }
    part[t] = s;
    __syncthreads();
    for (int off = 1; off < 1024; off <<= 1) {
        int v = (t >= off) ? part[t - off] : 0;
        __syncthreads();
        part[t] += v;
        __syncthreads();
    }
    int run = (t == 0) ? 0 : part[t - 1];
    for (int j = 0; j < C; j++) {
        int idx = t * C + j;
        if (idx < N_NODES) {
            int d = g_deg[idx];
            g_rowptr[idx] = run;
            g_cursor[idx] = run;
            g_dinv[idx]   = rsqrtf((float)(d + 1));
            run += d;
        }
    }
    if (t == 1023) g_rowptr[N_NODES] = run;
}

__global__ __launch_bounds__(256) void fill_kernel(const int* __restrict__ ei) {
    int e = blockIdx.x * blockDim.x + threadIdx.x;
    if (e < N_EDGES) {
        int s = ei[e];
        int d = ei[N_EDGES + e];
        int pos = atomicAdd(&g_cursor[d], 1);
        g_col[pos] = s;
    }
}

// ---------------- weights -> fp16 (once per call) ---------------------------
__global__ __launch_bounds__(256) void wprep_kernel(const float* __restrict__ W1,
                                                    const float* __restrict__ W2,
                                                    const float* __restrict__ W3,
                                                    const float* __restrict__ W4) {
    int i = blockIdx.x * blockDim.x + threadIdx.x;
    if (i < 3072)                 g_wh[i] = __float2half(W1[i]);
    else if (i < 3072 + 9216)     g_wh[i] = __float2half(W2[i - 3072]);
    else if (i < 3072 + 2 * 9216) g_wh[i] = __float2half(W3[i - 3072 - 9216]);
    else if (i < 3072 + 3 * 9216) g_wh[i] = __float2half(W4[i - 3072 - 2 * 9216]);
}

// ---------------- xs0 = half(x * dinv)  [N,32] ------------------------------
__global__ __launch_bounds__(256) void scale0_kernel(const float* __restrict__ x,
                                                     __half* __restrict__ out) {
    int idx = blockIdx.x * blockDim.x + threadIdx.x;
    if (idx < N_NODES * 8) {
        int node = idx >> 3;
        float d = g_dinv[node];
        float4 v = ((const float4*)x)[idx];
        v.x *= d; v.y *= d; v.z *= d; v.w *= d;
        ((uint2*)out)[idx] = f4_to_h4(v);
    }
}

// ---------------- aggregation (fp16 in, fp32 acc, fp16 out, MLP-unrolled) --
// U2 = uint2 (4 halves) per node row.  U2==8: 4 nodes/warp.  U2==24: 1 node/warp.
template <int U2>
__global__ __launch_bounds__(256) void agg_kernel(const __half* __restrict__ xs,
                                                  __half* __restrict__ out) {
    int gtid = blockIdx.x * blockDim.x + threadIdx.x;
    int warp = gtid >> 5;
    int lane = threadIdx.x & 31;
    int node, f;
    if (U2 == 8) { node = warp * 4 + (lane >> 3); f = lane & 7; }
    else         { node = warp; f = lane; if (f >= U2) return; }
    if (node >= N_NODES) return;

    const uint2* x2 = (const uint2*)xs;
    float4 acc = h4_to_f4(x2[(long)node * U2 + f]);   // self term
    int e0 = g_rowptr[node];
    int e1 = g_rowptr[node + 1];
    int e  = e0;

    const int UNROLL = (U2 == 24) ? 8 : 4;
    for (; e + UNROLL <= e1; e += UNROLL) {
        int s[UNROLL];
#pragma unroll
        for (int j = 0; j < UNROLL; j++) s[j] = __ldg(&g_col[e + j]);
        uint2 u[UNROLL];
#pragma unroll
        for (int j = 0; j < UNROLL; j++) u[j] = __ldg(&x2[(long)s[j] * U2 + f]);
#pragma unroll
        for (int j = 0; j < UNROLL; j++) {
            float4 v = h4_to_f4(u[j]);
            acc.x += v.x; acc.y += v.y; acc.z += v.z; acc.w += v.w;
        }
    }
    for (; e < e1; e++) {
        int s = __ldg(&g_col[e]);
        float4 v = h4_to_f4(__ldg(&x2[(long)s * U2 + f]));
        acc.x += v.x; acc.y += v.y; acc.z += v.z; acc.w += v.w;
    }
    float d = g_dinv[node];
    acc.x *= d; acc.y *= d; acc.z *= d; acc.w *= d;
    ((uint2*)out)[(long)node * U2 + f] = f4_to_h4(acc);
}

// ---------------- wmma fp16 GEMM -------------------------------------------
// C[row0..row0+127, 0..95] = half( act( A[128,KD] @ W[KD,96] + b ) (* dinv) )
// 256 threads = 8 warps; warp tile 32 rows x 48 cols (2x3 m16n16k16 frags).
template <int KD, bool SCALE>
__global__ __launch_bounds__(256) void gemm_wmma(const __half* __restrict__ A,
                                                 __half* __restrict__ C,
                                                 const __half* __restrict__ Wh,
                                                 const float* __restrict__ b) {
    extern __shared__ __align__(16) char smem[];
    const int KP = KD + 8;                       // padded A stride (halves)
    __half* sA = (__half*)smem;                  // 128 * KP halves
    __half* sW = (__half*)(smem + 128 * KP * 2); // KD * 96 halves
    float*  sC = (float*)smem;                   // reused: 128 * 96 floats
    float*  sB = (float*)(smem + 128 * 96 * 4);  // 96 floats

    int tid = threadIdx.x, wid = tid >> 5;
    int row0 = blockIdx.x * 128;

    // stage W (already fp16): uint4 copies
    for (int i = tid; i < KD * 12; i += 256)
        ((uint4*)sW)[i] = ((const uint4*)Wh)[i];
    if (tid < 96) sB[tid] = b[tid];

    // stage A (already half): uint4 copies, zero-fill tail rows
    const int RU4 = KD / 8;                      // uint4 per row
    for (int i = tid; i < 128 * RU4; i += 256) {
        int r = i / RU4, c = i % RU4;
        int gr = row0 + r;
        uint4 v = make_uint4(0u, 0u, 0u, 0u);
        if (gr < N_NODES) v = ((const uint4*)A)[(long)gr * RU4 + c];
        *(uint4*)&sA[r * KP + c * 8] = v;
    }
    __syncthreads();

    const int wm = (wid >> 1) * 32;   // warp row offset: 0/32/64/96
    const int wn = (wid & 1) * 48;    // warp col offset: 0/48

    wmma::fragment<wmma::accumulator, 16, 16, 16, float> acc[2][3];
#pragma unroll
    for (int i = 0; i < 2; i++)
#pragma unroll
        for (int j = 0; j < 3; j++) wmma::fill_fragment(acc[i][j], 0.f);

#pragma unroll
    for (int k0 = 0; k0 < KD; k0 += 16) {
        wmma::fragment<wmma::matrix_a, 16, 16, 16, __half, wmma::row_major> af[2];
        wmma::fragment<wmma::matrix_b, 16, 16, 16, __half, wmma::row_major> bf[3];
#pragma unroll
        for (int i = 0; i < 2; i++)
            wmma::load_matrix_sync(af[i], &sA[(wm + i * 16) * KP + k0], KP);
#pragma unroll
        for (int j = 0; j < 3; j++)
            wmma::load_matrix_sync(bf[j], &sW[k0 * 96 + wn + j * 16], 96);
#pragma unroll
        for (int i = 0; i < 2; i++)
#pragma unroll
            for (int j = 0; j < 3; j++)
                wmma::mma_sync(acc[i][j], af[i], bf[j], acc[i][j]);
    }

    __syncthreads();   // done reading sA/sW; reuse as C staging
#pragma unroll
    for (int i = 0; i < 2; i++)
#pragma unroll
        for (int j = 0; j < 3; j++)
            wmma::store_matrix_sync(&sC[(wm + i * 16) * 96 + wn + j * 16],
                                    acc[i][j], 96, wmma::mem_row_major);
    __syncthreads();

    // fused epilogue: bias + relu (+ dinv) -> half, coalesced uint2 stores
    for (int i = tid; i < 128 * 24; i += 256) {
        int r = i / 24, c2 = i % 24;
        int row = row0 + r;
        if (row >= N_NODES) continue;
        float d = SCALE ? g_dinv[row] : 1.f;
        const float* p = &sC[r * 96 + c2 * 4];
        float4 v;
        int c = c2 * 4;
        v.x = fmaxf(p[0] + sB[c + 0], 0.f) * d;
        v.y = fmaxf(p[1] + sB[c + 1], 0.f) * d;
        v.z = fmaxf(p[2] + sB[c + 2], 0.f) * d;
        v.w = fmaxf(p[3] + sB[c + 3], 0.f) * d;
        ((uint2*)&C[(long)row * 96])[c2] = f4_to_h4(v);
    }
}

// ---------------- global add pool ------------------------------------------
__global__ __launch_bounds__(256) void zero_pool_kernel() {
    int i = blockIdx.x * blockDim.x + threadIdx.x;
    if (i < N_GRAPHS * HID / 4) ((float4*)g_pool)[i] = make_float4(0.f, 0.f, 0.f, 0.f);
}

__global__ __launch_bounds__(256) void pool_kernel(const int* __restrict__ batch,
                                                   const __half* __restrict__ h) {
    const int CH = 32;
    int warp = (blockIdx.x * blockDim.x + threadIdx.x) >> 5;
    int lane = threadIdx.x & 31;
    if (lane >= 24) return;
    int n0 = warp * CH;
    if (n0 >= N_NODES) return;
    int n1 = min(n0 + CH, N_NODES);

    const uint2* h2 = (const uint2*)h;
    int cur = batch[n0];
    float4 acc = make_float4(0.f, 0.f, 0.f, 0.f);
    for (int n = n0; n < n1; n++) {
        int bg = batch[n];
        if (bg != cur) {
            float* p = &g_pool[cur * HID + lane * 4];
            atomicAdd(p + 0, acc.x); atomicAdd(p + 1, acc.y);
            atomicAdd(p + 2, acc.z); atomicAdd(p + 3, acc.w);
            acc = make_float4(0.f, 0.f, 0.f, 0.f);
            cur = bg;
        }
        float4 v = h4_to_f4(h2[(long)n * 24 + lane]);
        acc.x += v.x; acc.y += v.y; acc.z += v.z; acc.w += v.w;
    }
    float* p = &g_pool[cur * HID + lane * 4];
    atomicAdd(p + 0, acc.x); atomicAdd(p + 1, acc.y);
    atomicAdd(p + 2, acc.z); atomicAdd(p + 3, acc.w);
}

// ---------------- final MLP ------------------------------------------------
__global__ __launch_bounds__(128) void mlp_kernel(const float* __restrict__ Wf1,
                                                  const float* __restrict__ bf1,
                                                  const float* __restrict__ Wf2,
                                                  const float* __restrict__ bf2,
                                                  float* __restrict__ out) {
    int g = blockIdx.x * 4 + (threadIdx.x >> 5);
    int j = threadIdx.x & 31;
    if (g >= N_GRAPHS) return;
    float hj = bf1[j];
    const float* gp = &g_pool[g * HID];
#pragma unroll 8
    for (int i = 0; i < 96; i++) hj += gp[i] * Wf1[i * 32 + j];
    hj = fmaxf(hj, 0.f);
    float v = hj * Wf2[j];
#pragma unroll
    for (int off = 16; off; off >>= 1) v += __shfl_down_sync(0xffffffffu, v, off);
    if (j == 0) out[g] = v + bf2[0];
}

// ---------------- launch ---------------------------------------------------
extern "C" void kernel_launch(void* const* d_in, const int* in_sizes, int n_in,
                              void* d_out, int out_size) {
    const float* x     = (const float*)d_in[0];
    const int*   ei    = (const int*)d_in[1];
    const int*   batch = (const int*)d_in[2];
    const float* W1  = (const float*)d_in[3];
    const float* b1  = (const float*)d_in[4];
    const float* W2  = (const float*)d_in[5];
    const float* b2  = (const float*)d_in[6];
    const float* W3  = (const float*)d_in[7];
    const float* b3  = (const float*)d_in[8];
    const float* W4  = (const float*)d_in[9];
    const float* b4  = (const float*)d_in[10];
    const float* Wf1 = (const float*)d_in[11];
    const float* bf1 = (const float*)d_in[12];
    const float* Wf2 = (const float*)d_in[13];
    const float* bf2 = (const float*)d_in[14];
    float* out = (float*)d_out;

    __half *bufA, *bufB, *wh;
    cudaGetSymbolAddress((void**)&bufA, g_bufA);
    cudaGetSymbolAddress((void**)&bufB, g_bufB);
    cudaGetSymbolAddress((void**)&wh, g_wh);

    const int SM = 128 * 96 * 4 + 96 * 4;   // 49536 B
    cudaFuncSetAttribute(gemm_wmma<96, true>,  cudaFuncAttributeMaxDynamicSharedMemorySize, SM);
    cudaFuncSetAttribute(gemm_wmma<96, false>, cudaFuncAttributeMaxDynamicSharedMemorySize, SM);
    cudaFuncSetAttribute(gemm_wmma<32, true>,  cudaFuncAttributeMaxDynamicSharedMemorySize, SM);

    const int TB = 256;
    int nb_nodes = (N_NODES + TB - 1) / TB;
    int nb_edges = (N_EDGES + TB - 1) / TB;

    // CSR build
    zero_deg_kernel<<<nb_nodes, TB>>>();
    count_kernel<<<nb_edges, TB>>>(ei);
    scan_kernel<<<1, 1024>>>();
    fill_kernel<<<nb_edges, TB>>>(ei);

    // weights -> fp16, xs0 = half(x * dinv)
    wprep_kernel<<<(3072 + 3 * 9216 + TB - 1) / TB, TB>>>(W1, W2, W3, W4);
    scale0_kernel<<<(N_NODES * 8 + TB - 1) / TB, TB>>>(x, bufA);

    const int AGG8_BLKS  = (N_NODES / 4 * 32 + TB - 1) / TB;
    const int AGG24_BLKS = ((long)N_NODES * 32 + TB - 1) / TB;
    const int GEMM_BLKS  = (N_NODES + 127) / 128;   // 782

    // layer 1
    agg_kernel<8><<<AGG8_BLKS, TB>>>(bufA, bufB);
    gemm_wmma<32, true><<<GEMM_BLKS, 256, SM>>>(bufB, bufA, wh, b1);
    // layer 2
    agg_kernel<24><<<AGG24_BLKS, TB>>>(bufA, bufB);
    gemm_wmma<96, true><<<GEMM_BLKS, 256, SM>>>(bufB, bufA, wh + 3072, b2);
    // layer 3
    agg_kernel<24><<<AGG24_BLKS, TB>>>(bufA, bufB);
    gemm_wmma<96, true><<<GEMM_BLKS, 256, SM>>>(bufB, bufA, wh + 3072 + 9216, b3);
    // layer 4
    agg_kernel<24><<<AGG24_BLKS, TB>>>(bufA, bufB);
    gemm_wmma<96, false><<<GEMM_BLKS, 256, SM>>>(bufB, bufA, wh + 3072 + 2 * 9216, b4);

    // pool + MLP
    zero_pool_kernel<<<(N_GRAPHS * HID / 4 + TB - 1) / TB, TB>>>();
    int pool_warps = (N_NODES + 31) / 32;
    pool_kernel<<<(pool_warps * 32 + TB - 1) / TB, TB>>>(batch, bufA);
    mlp_kernel<<<N_GRAPHS / 4, 128>>>(Wf1, bf1, Wf2, bf2, out);
}

// round 7
// speedup vs baseline: 1.8072x; 1.5250x over previous
#include <cuda_runtime.h>
#include <cuda_fp16.h>
#include <mma.h>
#include <cstdint>

using namespace nvcuda;

#define N_NODES  100000
#define N_EDGES  1600000
#define HID      96
#define N_GRAPHS 2048
#define NB       391        // ceil(N_NODES/256)

// ---------------- scratch (device globals; no allocation allowed) ----------
__device__ int    g_deg[N_NODES];
__device__ int    g_rowptr[N_NODES + 1];
__device__ int    g_cursor[N_NODES];
__device__ int    g_col[N_EDGES];
__device__ float  g_dinv[N_NODES];
__device__ __half g_bufA[N_NODES * HID];
__device__ __half g_bufB[N_NODES * HID];
__device__ float  g_pool[N_GRAPHS * HID];
__device__ __half g_wh[3072 + 3 * 9216];   // W1(32x96), W2..W4(96x96) fp16
__device__ int    g_bsum[512];
__device__ int    g_boff[512];

// ---------------- half4 helpers --------------------------------------------
__device__ __forceinline__ float4 h4_to_f4(uint2 u) {
    __half2 a = *reinterpret_cast<__half2*>(&u.x);
    __half2 b = *reinterpret_cast<__half2*>(&u.y);
    float2 fa = __half22float2(a), fb = __half22float2(b);
    return make_float4(fa.x, fa.y, fb.x, fb.y);
}
__device__ __forceinline__ uint2 f4_to_h4(float4 v) {
    __half2 a = __floats2half2_rn(v.x, v.y);
    __half2 b = __floats2half2_rn(v.z, v.w);
    uint2 u;
    u.x = *reinterpret_cast<uint32_t*>(&a);
    u.y = *reinterpret_cast<uint32_t*>(&b);
    return u;
}

// ---------------- CSR build ------------------------------------------------
__global__ __launch_bounds__(256) void zero_deg_kernel() {
    int i = blockIdx.x * blockDim.x + threadIdx.x;
    if (i < N_NODES) g_deg[i] = 0;
}

__global__ __launch_bounds__(256) void count_kernel(const int* __restrict__ ei) {
    int e = blockIdx.x * blockDim.x + threadIdx.x;
    if (e < N_EDGES) atomicAdd(&g_deg[ei[N_EDGES + e]], 1);
}

// phase A: per-block sums (coalesced)
__global__ __launch_bounds__(256) void scanA_kernel() {
    __shared__ int sh[256];
    int t = threadIdx.x;
    int i = blockIdx.x * 256 + t;
    sh[t] = (i < N_NODES) ? g_deg[i] : 0;
    __syncthreads();
    for (int o = 128; o; o >>= 1) {
        if (t < o) sh[t] += sh[t + o];
        __syncthreads();
    }
    if (t == 0) g_bsum[blockIdx.x] = sh[0];
}

// phase B: scan 391 block sums (1 block)
__global__ __launch_bounds__(512) void scanB_kernel() {
    __shared__ int sh[512];
    int t = threadIdx.x;
    int v = (t < NB) ? g_bsum[t] : 0;
    sh[t] = v;
    __syncthreads();
    for (int o = 1; o < 512; o <<= 1) {
        int u = (t >= o) ? sh[t - o] : 0;
        __syncthreads();
        sh[t] += u;
        __syncthreads();
    }
    g_boff[t] = sh[t] - v;   // exclusive
}

// phase C: block-local scan + emit rowptr/cursor/dinv (coalesced)
__global__ __launch_bounds__(256) void scanC_kernel() {
    __shared__ int sh[256];
    int t = threadIdx.x;
    int i = blockIdx.x * 256 + t;
    int d = (i < N_NODES) ? g_deg[i] : 0;
    sh[t] = d;
    __syncthreads();
    for (int o = 1; o < 256; o <<= 1) {
        int u = (t >= o) ? sh[t - o] : 0;
        __syncthreads();
        sh[t] += u;
        __syncthreads();
    }
    int excl = sh[t] - d;
    if (i < N_NODES) {
        int rp = g_boff[blockIdx.x] + excl;
        g_rowptr[i] = rp;
        g_cursor[i] = rp;
        g_dinv[i]   = rsqrtf((float)(d + 1));
    }
    if (i == 0) g_rowptr[N_NODES] = N_EDGES;
}

__global__ __launch_bounds__(256) void fill_kernel(const int* __restrict__ ei) {
    int e = blockIdx.x * blockDim.x + threadIdx.x;
    if (e < N_EDGES) {
        int s = ei[e];
        int d = ei[N_EDGES + e];
        int pos = atomicAdd(&g_cursor[d], 1);
        g_col[pos] = s;
    }
}

// ---------------- weights -> fp16 ------------------------------------------
__global__ __launch_bounds__(256) void wprep_kernel(const float* __restrict__ W1,
                                                    const float* __restrict__ W2,
                                                    const float* __restrict__ W3,
                                                    const float* __restrict__ W4) {
    int i = blockIdx.x * blockDim.x + threadIdx.x;
    if (i < 3072)                 g_wh[i] = __float2half(W1[i]);
    else if (i < 3072 + 9216)     g_wh[i] = __float2half(W2[i - 3072]);
    else if (i < 3072 + 2 * 9216) g_wh[i] = __float2half(W3[i - 3072 - 9216]);
    else if (i < 3072 + 3 * 9216) g_wh[i] = __float2half(W4[i - 3072 - 2 * 9216]);
}

// ---------------- xs0 = half(x * dinv) [N,32] -------------------------------
__global__ __launch_bounds__(256) void scale0_kernel(const float* __restrict__ x,
                                                     __half* __restrict__ out) {
    int idx = blockIdx.x * blockDim.x + threadIdx.x;
    if (idx < N_NODES * 8) {
        int node = idx >> 3;
        float d = g_dinv[node];
        float4 v = ((const float4*)x)[idx];
        v.x *= d; v.y *= d; v.z *= d; v.w *= d;
        ((uint2*)out)[idx] = f4_to_h4(v);
    }
}

__global__ __launch_bounds__(256) void zero_pool_kernel() {
    int i = blockIdx.x * blockDim.x + threadIdx.x;
    if (i < N_GRAPHS * HID / 4) ((float4*)g_pool)[i] = make_float4(0.f, 0.f, 0.f, 0.f);
}

// ---------------- fused layer: aggregate + wmma GEMM + epilogue -------------
// Block = 128 nodes, 256 threads (8 warps).
// Phase A: warp w aggregates nodes w*16..w*16+15 into sA (fp16, padded KP).
// Phase B: wmma fp16 m16n16k16, warp tile 32x48.
// Phase C: epilogue -> Xout (bias,relu,*dinv) or pooled atomics (layer 4).
template <int KD, bool SCALE_OUT, bool POOL>
__global__ __launch_bounds__(256) void gcn_layer(const __half* __restrict__ Xin,
                                                 __half* __restrict__ Xout,
                                                 const __half* __restrict__ Wh,
                                                 const float* __restrict__ b,
                                                 const int* __restrict__ batch) {
    extern __shared__ __align__(16) char smem[];
    const int KP = KD + 8;
    __half* sA = (__half*)smem;                    // 128*KP halves
    __half* sW = (__half*)(smem + 128 * KP * 2);   // KD*96 halves
    float*  sC = (float*)smem;                     // overlay: 128*96 floats
    float*  sB = (float*)(smem + 49152);           // 96 floats
    int*    sBatch = (int*)(smem + 49152 + 384);   // 128 ints

    const int tid = threadIdx.x, wid = tid >> 5, lane = tid & 31;
    const int row0 = blockIdx.x * 128;

    // stage W + bias (+batch)
    for (int i = tid; i < KD * 12; i += 256)
        ((uint4*)sW)[i] = ((const uint4*)Wh)[i];
    if (tid < 96) sB[tid] = b[tid];
    if (POOL)
        for (int i = tid; i < 128; i += 256)
            sBatch[i] = (row0 + i < N_NODES) ? batch[row0 + i] : -1;

    // ---- phase A: aggregation into sA ----
    const uint2* x2 = (const uint2*)Xin;
    if (KD == 96) {
        if (lane < 24) {
            const int f = lane;
            for (int rr = 0; rr < 16; rr++) {
                int r = wid * 16 + rr;
                int node = row0 + r;
                float4 acc = make_float4(0.f, 0.f, 0.f, 0.f);
                if (node < N_NODES) {
                    acc = h4_to_f4(x2[(long)node * 24 + f]);
                    int e0 = g_rowptr[node], e1 = g_rowptr[node + 1];
                    int e = e0;
                    for (; e + 8 <= e1; e += 8) {
                        int s[8];
#pragma unroll
                        for (int j = 0; j < 8; j++) s[j] = __ldg(&g_col[e + j]);
                        uint2 u[8];
#pragma unroll
                        for (int j = 0; j < 8; j++) u[j] = __ldg(&x2[(long)s[j] * 24 + f]);
#pragma unroll
                        for (int j = 0; j < 8; j++) {
                            float4 v = h4_to_f4(u[j]);
                            acc.x += v.x; acc.y += v.y; acc.z += v.z; acc.w += v.w;
                        }
                    }
                    for (; e < e1; e++) {
                        int s = __ldg(&g_col[e]);
                        float4 v = h4_to_f4(__ldg(&x2[(long)s * 24 + f]));
                        acc.x += v.x; acc.y += v.y; acc.z += v.z; acc.w += v.w;
                    }
                    float d = g_dinv[node];
                    acc.x *= d; acc.y *= d; acc.z *= d; acc.w *= d;
                }
                *(uint2*)&sA[r * KP + f * 4] = f4_to_h4(acc);
            }
        }
    } else {  // KD == 32: 4 nodes per warp in parallel, 8 lanes each
        const int f = lane & 7, sub = lane >> 3;
        for (int g4 = 0; g4 < 4; g4++) {
            int r = wid * 16 + g4 * 4 + sub;
            int node = row0 + r;
            float4 acc = make_float4(0.f, 0.f, 0.f, 0.f);
            if (node < N_NODES) {
                acc = h4_to_f4(x2[(long)node * 8 + f]);
                int e0 = g_rowptr[node], e1 = g_rowptr[node + 1];
                int e = e0;
                for (; e + 4 <= e1; e += 4) {
                    int s[4];
#pragma unroll
                    for (int j = 0; j < 4; j++) s[j] = __ldg(&g_col[e + j]);
                    uint2 u[4];
#pragma unroll
                    for (int j = 0; j < 4; j++) u[j] = __ldg(&x2[(long)s[j] * 8 + f]);
#pragma unroll
                    for (int j = 0; j < 4; j++) {
                        float4 v = h4_to_f4(u[j]);
                        acc.x += v.x; acc.y += v.y; acc.z += v.z; acc.w += v.w;
                    }
                }
                for (; e < e1; e++) {
                    int s = __ldg(&g_col[e]);
                    float4 v = h4_to_f4(__ldg(&x2[(long)s * 8 + f]));
                    acc.x += v.x; acc.y += v.y; acc.z += v.z; acc.w += v.w;
                }
                float d = g_dinv[node];
                acc.x *= d; acc.y *= d; acc.z *= d; acc.w *= d;
            }
            *(uint2*)&sA[r * KP + f * 4] = f4_to_h4(acc);
        }
    }
    __syncthreads();

    // ---- phase B: wmma ----
    const int wm = (wid >> 1) * 32;
    const int wn = (wid & 1) * 48;

    wmma::fragment<wmma::accumulator, 16, 16, 16, float> acc[2][3];
#pragma unroll
    for (int i = 0; i < 2; i++)
#pragma unroll
        for (int j = 0; j < 3; j++) wmma::fill_fragment(acc[i][j], 0.f);

#pragma unroll
    for (int k0 = 0; k0 < KD; k0 += 16) {
        wmma::fragment<wmma::matrix_a, 16, 16, 16, __half, wmma::row_major> af[2];
        wmma::fragment<wmma::matrix_b, 16, 16, 16, __half, wmma::row_major> bf[3];
#pragma unroll
        for (int i = 0; i < 2; i++)
            wmma::load_matrix_sync(af[i], &sA[(wm + i * 16) * KP + k0], KP);
#pragma unroll
        for (int j = 0; j < 3; j++)
            wmma::load_matrix_sync(bf[j], &sW[k0 * 96 + wn + j * 16], 96);
#pragma unroll
        for (int i = 0; i < 2; i++)
#pragma unroll
            for (int j = 0; j < 3; j++)
                wmma::mma_sync(acc[i][j], af[i], bf[j], acc[i][j]);
    }

    __syncthreads();   // reuse smem as sC
#pragma unroll
    for (int i = 0; i < 2; i++)
#pragma unroll
        for (int j = 0; j < 3; j++)
            wmma::store_matrix_sync(&sC[(wm + i * 16) * 96 + wn + j * 16],
                                    acc[i][j], 96, wmma::mem_row_major);
    __syncthreads();

    // ---- phase C: epilogue ----
    if (!POOL) {
        for (int i = tid; i < 128 * 24; i += 256) {
            int r = i / 24, c2 = i % 24;
            int row = row0 + r;
            if (row >= N_NODES) continue;
            float d = SCALE_OUT ? g_dinv[row] : 1.f;
            const float* p = &sC[r * 96 + c2 * 4];
            float4 v;
            int c = c2 * 4;
            v.x = fmaxf(p[0] + sB[c + 0], 0.f) * d;
            v.y = fmaxf(p[1] + sB[c + 1], 0.f) * d;
            v.z = fmaxf(p[2] + sB[c + 2], 0.f) * d;
            v.w = fmaxf(p[3] + sB[c + 3], 0.f) * d;
            ((uint2*)&Xout[(long)row * 96])[c2] = f4_to_h4(v);
        }
    } else {
        // pooled epilogue: warp w owns rows w*16..+15, lane owns 3 columns
        int rbase = wid * 16;
        if (row0 + rbase < N_NODES) {
            int c = lane * 3;
            float b0 = sB[c], b1 = sB[c + 1], b2 = sB[c + 2];
            int cur = sBatch[rbase];
            float a0 = 0.f, a1 = 0.f, a2 = 0.f;
            for (int rr = 0; rr < 16; rr++) {
                int r = rbase + rr;
                if (row0 + r >= N_NODES) break;
                int bg = sBatch[r];
                if (bg != cur) {
                    atomicAdd(&g_pool[cur * 96 + c + 0], a0);
                    atomicAdd(&g_pool[cur * 96 + c + 1], a1);
                    atomicAdd(&g_pool[cur * 96 + c + 2], a2);
                    a0 = a1 = a2 = 0.f;
                    cur = bg;
                }
                const float* p = &sC[r * 96 + c];
                a0 += fmaxf(p[0] + b0, 0.f);
                a1 += fmaxf(p[1] + b1, 0.f);
                a2 += fmaxf(p[2] + b2, 0.f);
            }
            atomicAdd(&g_pool[cur * 96 + c + 0], a0);
            atomicAdd(&g_pool[cur * 96 + c + 1], a1);
            atomicAdd(&g_pool[cur * 96 + c + 2], a2);
        }
    }
}

// ---------------- final MLP ------------------------------------------------
__global__ __launch_bounds__(128) void mlp_kernel(const float* __restrict__ Wf1,
                                                  const float* __restrict__ bf1,
                                                  const float* __restrict__ Wf2,
                                                  const float* __restrict__ bf2,
                                                  float* __restrict__ out) {
    int g = blockIdx.x * 4 + (threadIdx.x >> 5);
    int j = threadIdx.x & 31;
    if (g >= N_GRAPHS) return;
    float hj = bf1[j];
    const float* gp = &g_pool[g * HID];
#pragma unroll 8
    for (int i = 0; i < 96; i++) hj += gp[i] * Wf1[i * 32 + j];
    hj = fmaxf(hj, 0.f);
    float v = hj * Wf2[j];
#pragma unroll
    for (int off = 16; off; off >>= 1) v += __shfl_down_sync(0xffffffffu, v, off);
    if (j == 0) out[g] = v + bf2[0];
}

// ---------------- launch ---------------------------------------------------
extern "C" void kernel_launch(void* const* d_in, const int* in_sizes, int n_in,
                              void* d_out, int out_size) {
    const float* x     = (const float*)d_in[0];
    const int*   ei    = (const int*)d_in[1];
    const int*   batch = (const int*)d_in[2];
    const float* W1  = (const float*)d_in[3];
    const float* b1  = (const float*)d_in[4];
    const float* W2  = (const float*)d_in[5];
    const float* b2  = (const float*)d_in[6];
    const float* W3  = (const float*)d_in[7];
    const float* b3  = (const float*)d_in[8];
    const float* W4  = (const float*)d_in[9];
    const float* b4  = (const float*)d_in[10];
    const float* Wf1 = (const float*)d_in[11];
    const float* bf1 = (const float*)d_in[12];
    const float* Wf2 = (const float*)d_in[13];
    const float* bf2 = (const float*)d_in[14];
    float* out = (float*)d_out;

    __half *bufA, *bufB, *wh;
    cudaGetSymbolAddress((void**)&bufA, g_bufA);
    cudaGetSymbolAddress((void**)&bufB, g_bufB);
    cudaGetSymbolAddress((void**)&wh, g_wh);

    const int SM = 49152 + 384 + 512;   // 50048 B
    cudaFuncSetAttribute((const void*)gcn_layer<32, true,  false>, cudaFuncAttributeMaxDynamicSharedMemorySize, SM);
    cudaFuncSetAttribute((const void*)gcn_layer<96, true,  false>, cudaFuncAttributeMaxDynamicSharedMemorySize, SM);
    cudaFuncSetAttribute((const void*)gcn_layer<96, false, true >, cudaFuncAttributeMaxDynamicSharedMemorySize, SM);

    const int TB = 256;
    int nb_edges = (N_EDGES + TB - 1) / TB;

    // CSR build
    zero_deg_kernel<<<NB, TB>>>();
    count_kernel<<<nb_edges, TB>>>(ei);
    scanA_kernel<<<NB, TB>>>();
    scanB_kernel<<<1, 512>>>();
    scanC_kernel<<<NB, TB>>>();
    fill_kernel<<<nb_edges, TB>>>(ei);

    // prep
    wprep_kernel<<<(3072 + 3 * 9216 + TB - 1) / TB, TB>>>(W1, W2, W3, W4);
    scale0_kernel<<<(N_NODES * 8 + TB - 1) / TB, TB>>>(x, bufA);
    zero_pool_kernel<<<(N_GRAPHS * HID / 4 + TB - 1) / TB, TB>>>();

    const int L_BLKS = (N_NODES + 127) / 128;   // 782

    gcn_layer<32, true,  false><<<L_BLKS, 256, SM>>>(bufA, bufB, wh,                    b1, batch);
    gcn_layer<96, true,  false><<<L_BLKS, 256, SM>>>(bufB, bufA, wh + 3072,             b2, batch);
    gcn_layer<96, true,  false><<<L_BLKS, 256, SM>>>(bufA, bufB, wh + 3072 + 9216,      b3, batch);
    gcn_layer<96, false, true ><<<L_BLKS, 256, SM>>>(bufB, bufA, wh + 3072 + 2 * 9216,  b4, batch);

    mlp_kernel<<<N_GRAPHS / 4, 128>>>(Wf1, bf1, Wf2, bf2, out);
}

// round 8
// speedup vs baseline: 1.8357x; 1.0157x over previous
#include <cuda_runtime.h>
#include <cuda_fp16.h>
#include <mma.h>
#include <cstdint>

using namespace nvcuda;

#define N_NODES  100000
#define N_EDGES  1600000
#define HID      96
#define N_GRAPHS 2048
#define NB       391        // ceil(N_NODES/256)

// ---------------- scratch (device globals; no allocation allowed) ----------
__device__ int    g_deg[N_NODES];
__device__ int    g_rowptr[N_NODES + 1];
__device__ int    g_tick[N_EDGES];
__device__ int    g_col[N_EDGES];
__device__ float  g_dinv[N_NODES];
__device__ __half g_bufA[N_NODES * HID];
__device__ __half g_bufB[N_NODES * HID];
__device__ float  g_pool[N_GRAPHS * HID];
__device__ __half g_wh[3072 + 3 * 9216];   // W1(32x96), W2..W4(96x96) fp16
__device__ int    g_bsum[NB];

// ---------------- half4 helpers --------------------------------------------
__device__ __forceinline__ float4 h4_to_f4(uint2 u) {
    __half2 a = *reinterpret_cast<__half2*>(&u.x);
    __half2 b = *reinterpret_cast<__half2*>(&u.y);
    float2 fa = __half22float2(a), fb = __half22float2(b);
    return make_float4(fa.x, fa.y, fb.x, fb.y);
}
__device__ __forceinline__ uint2 f4_to_h4(float4 v) {
    __half2 a = __floats2half2_rn(v.x, v.y);
    __half2 b = __floats2half2_rn(v.z, v.w);
    uint2 u;
    u.x = *reinterpret_cast<uint32_t*>(&a);
    u.y = *reinterpret_cast<uint32_t*>(&b);
    return u;
}

// ---------------- fused prep: zero deg, zero pool, W->fp16 ------------------
__global__ __launch_bounds__(256) void prep_kernel(const float* __restrict__ W1,
                                                   const float* __restrict__ W2,
                                                   const float* __restrict__ W3,
                                                   const float* __restrict__ W4) {
    int i = blockIdx.x * blockDim.x + threadIdx.x;
    if (i < N_NODES) g_deg[i] = 0;
    if (i < N_GRAPHS * HID / 4)
        ((float4*)g_pool)[i] = make_float4(0.f, 0.f, 0.f, 0.f);
    if (i < 3072)                 g_wh[i] = __float2half(W1[i]);
    else if (i < 3072 + 9216)     g_wh[i] = __float2half(W2[i - 3072]);
    else if (i < 3072 + 2 * 9216) g_wh[i] = __float2half(W3[i - 3072 - 9216]);
    else if (i < 3072 + 3 * 9216) g_wh[i] = __float2half(W4[i - 3072 - 2 * 9216]);
}

// ---------------- CSR build ------------------------------------------------
// count + ticket: deg histogram, each edge remembers its slot within its dst.
__global__ __launch_bounds__(256) void count_kernel(const int* __restrict__ ei) {
    int e = blockIdx.x * blockDim.x + threadIdx.x;
    if (e < N_EDGES) {
        int d = ei[N_EDGES + e];
        g_tick[e] = atomicAdd(&g_deg[d], 1);
    }
}

// per-block sums of deg (coalesced)
__global__ __launch_bounds__(256) void scanA_kernel() {
    __shared__ int sh[256];
    int t = threadIdx.x;
    int i = blockIdx.x * 256 + t;
    sh[t] = (i < N_NODES) ? g_deg[i] : 0;
    __syncthreads();
    for (int o = 128; o; o >>= 1) {
        if (t < o) sh[t] += sh[t + o];
        __syncthreads();
    }
    if (t == 0) g_bsum[blockIdx.x] = sh[0];
}

// block-local scan + cross-block offset recomputed per block + emit rowptr/dinv
__global__ __launch_bounds__(256) void scanC_kernel() {
    __shared__ int sh[256];
    __shared__ int red[256];
    int t = threadIdx.x;
    int b = blockIdx.x;
    int i = b * 256 + t;
    int d = (i < N_NODES) ? g_deg[i] : 0;

    // cross-block offset: sum of g_bsum[j] for j < b
    int part = 0;
    if (t < b)                 part += g_bsum[t];
    if (t + 256 < b)           part += g_bsum[t + 256];
    red[t] = part;
    __syncthreads();
    for (int o = 128; o; o >>= 1) {
        if (t < o) red[t] += red[t + o];
        __syncthreads();
    }
    int boff = red[0];

    // local inclusive scan
    sh[t] = d;
    __syncthreads();
    for (int o = 1; o < 256; o <<= 1) {
        int u = (t >= o) ? sh[t - o] : 0;
        __syncthreads();
        sh[t] += u;
        __syncthreads();
    }
    if (i < N_NODES) {
        g_rowptr[i] = boff + sh[t] - d;
        g_dinv[i]   = rsqrtf((float)(d + 1));
    }
    if (i == 0) g_rowptr[N_NODES] = N_EDGES;
}

// fill: pure scatter, no atomics (uses stored tickets)
__global__ __launch_bounds__(256) void fill_kernel(const int* __restrict__ ei) {
    int e = blockIdx.x * blockDim.x + threadIdx.x;
    if (e < N_EDGES) {
        int s = ei[e];
        int d = ei[N_EDGES + e];
        g_col[g_rowptr[d] + g_tick[e]] = s;
    }
}

// ---------------- xs0 = half(x * dinv) [N,32] -------------------------------
__global__ __launch_bounds__(256) void scale0_kernel(const float* __restrict__ x,
                                                     __half* __restrict__ out) {
    int idx = blockIdx.x * blockDim.x + threadIdx.x;
    if (idx < N_NODES * 8) {
        int node = idx >> 3;
        float d = g_dinv[node];
        float4 v = ((const float4*)x)[idx];
        v.x *= d; v.y *= d; v.z *= d; v.w *= d;
        ((uint2*)out)[idx] = f4_to_h4(v);
    }
}

// ---------------- fused layer: aggregate + wmma GEMM + epilogue -------------
template <int KD, bool SCALE_OUT, bool POOL>
__global__ __launch_bounds__(256, 3) void gcn_layer(const __half* __restrict__ Xin,
                                                    __half* __restrict__ Xout,
                                                    const __half* __restrict__ Wh,
                                                    const float* __restrict__ b,
                                                    const int* __restrict__ batch) {
    extern __shared__ __align__(16) char smem[];
    const int KP = KD + 8;
    __half* sA = (__half*)smem;                    // 128*KP halves
    __half* sW = (__half*)(smem + 128 * KP * 2);   // KD*96 halves
    float*  sC = (float*)smem;                     // overlay: 128*96 floats
    float*  sB = (float*)(smem + 49152);           // 96 floats
    int*    sBatch = (int*)(smem + 49152 + 384);   // 128 ints

    const int tid = threadIdx.x, wid = tid >> 5, lane = tid & 31;
    const int row0 = blockIdx.x * 128;

    for (int i = tid; i < KD * 12; i += 256)
        ((uint4*)sW)[i] = ((const uint4*)Wh)[i];
    if (tid < 96) sB[tid] = b[tid];
    if (POOL)
        for (int i = tid; i < 128; i += 256)
            sBatch[i] = (row0 + i < N_NODES) ? batch[row0 + i] : -1;

    // ---- phase A: aggregation into sA ----
    const uint2* x2 = (const uint2*)Xin;
    if (KD == 96) {
        if (lane < 24) {
            const int f = lane;
            for (int rr = 0; rr < 16; rr++) {
                int r = wid * 16 + rr;
                int node = row0 + r;
                float4 acc = make_float4(0.f, 0.f, 0.f, 0.f);
                if (node < N_NODES) {
                    acc = h4_to_f4(x2[(long)node * 24 + f]);
                    int e0 = g_rowptr[node], e1 = g_rowptr[node + 1];
                    int e = e0;
                    for (; e + 8 <= e1; e += 8) {
                        int s[8];
#pragma unroll
                        for (int j = 0; j < 8; j++) s[j] = __ldg(&g_col[e + j]);
                        uint2 u[8];
#pragma unroll
                        for (int j = 0; j < 8; j++) u[j] = __ldg(&x2[(long)s[j] * 24 + f]);
#pragma unroll
                        for (int j = 0; j < 8; j++) {
                            float4 v = h4_to_f4(u[j]);
                            acc.x += v.x; acc.y += v.y; acc.z += v.z; acc.w += v.w;
                        }
                    }
                    for (; e < e1; e++) {
                        int s = __ldg(&g_col[e]);
                        float4 v = h4_to_f4(__ldg(&x2[(long)s * 24 + f]));
                        acc.x += v.x; acc.y += v.y; acc.z += v.z; acc.w += v.w;
                    }
                    float d = g_dinv[node];
                    acc.x *= d; acc.y *= d; acc.z *= d; acc.w *= d;
                }
                *(uint2*)&sA[r * KP + f * 4] = f4_to_h4(acc);
            }
        }
    } else {  // KD == 32: 4 nodes per warp in parallel, 8 lanes each
        const int f = lane & 7, sub = lane >> 3;
        for (int g4 = 0; g4 < 4; g4++) {
            int r = wid * 16 + g4 * 4 + sub;
            int node = row0 + r;
            float4 acc = make_float4(0.f, 0.f, 0.f, 0.f);
            if (node < N_NODES) {
                acc = h4_to_f4(x2[(long)node * 8 + f]);
                int e0 = g_rowptr[node], e1 = g_rowptr[node + 1];
                int e = e0;
                for (; e + 4 <= e1; e += 4) {
                    int s[4];
#pragma unroll
                    for (int j = 0; j < 4; j++) s[j] = __ldg(&g_col[e + j]);
                    uint2 u[4];
#pragma unroll
                    for (int j = 0; j < 4; j++) u[j] = __ldg(&x2[(long)s[j] * 8 + f]);
#pragma unroll
                    for (int j = 0; j < 4; j++) {
                        float4 v = h4_to_f4(u[j]);
                        acc.x += v.x; acc.y += v.y; acc.z += v.z; acc.w += v.w;
                    }
                }
                for (; e < e1; e++) {
                    int s = __ldg(&g_col[e]);
                    float4 v = h4_to_f4(__ldg(&x2[(long)s * 8 + f]));
                    acc.x += v.x; acc.y += v.y; acc.z += v.z; acc.w += v.w;
                }
                float d = g_dinv[node];
                acc.x *= d; acc.y *= d; acc.z *= d; acc.w *= d;
            }
            *(uint2*)&sA[r * KP + f * 4] = f4_to_h4(acc);
        }
    }
    __syncthreads();

    // ---- phase B: wmma ----
    const int wm = (wid >> 1) * 32;
    const int wn = (wid & 1) * 48;

    wmma::fragment<wmma::accumulator, 16, 16, 16, float> acc[2][3];
#pragma unroll
    for (int i = 0; i < 2; i++)
#pragma unroll
        for (int j = 0; j < 3; j++) wmma::fill_fragment(acc[i][j], 0.f);

#pragma unroll
    for (int k0 = 0; k0 < KD; k0 += 16) {
        wmma::fragment<wmma::matrix_a, 16, 16, 16, __half, wmma::row_major> af[2];
        wmma::fragment<wmma::matrix_b, 16, 16, 16, __half, wmma::row_major> bf[3];
#pragma unroll
        for (int i = 0; i < 2; i++)
            wmma::load_matrix_sync(af[i], &sA[(wm + i * 16) * KP + k0], KP);
#pragma unroll
        for (int j = 0; j < 3; j++)
            wmma::load_matrix_sync(bf[j], &sW[k0 * 96 + wn + j * 16], 96);
#pragma unroll
        for (int i = 0; i < 2; i++)
#pragma unroll
            for (int j = 0; j < 3; j++)
                wmma::mma_sync(acc[i][j], af[i], bf[j], acc[i][j]);
    }

    __syncthreads();   // reuse smem as sC
#pragma unroll
    for (int i = 0; i < 2; i++)
#pragma unroll
        for (int j = 0; j < 3; j++)
            wmma::store_matrix_sync(&sC[(wm + i * 16) * 96 + wn + j * 16],
                                    acc[i][j], 96, wmma::mem_row_major);
    __syncthreads();

    // ---- phase C: epilogue ----
    if (!POOL) {
        for (int i = tid; i < 128 * 24; i += 256) {
            int r = i / 24, c2 = i % 24;
            int row = row0 + r;
            if (row >= N_NODES) continue;
            float d = SCALE_OUT ? g_dinv[row] : 1.f;
            const float* p = &sC[r * 96 + c2 * 4];
            float4 v;
            int c = c2 * 4;
            v.x = fmaxf(p[0] + sB[c + 0], 0.f) * d;
            v.y = fmaxf(p[1] + sB[c + 1], 0.f) * d;
            v.z = fmaxf(p[2] + sB[c + 2], 0.f) * d;
            v.w = fmaxf(p[3] + sB[c + 3], 0.f) * d;
            ((uint2*)&Xout[(long)row * 96])[c2] = f4_to_h4(v);
        }
    } else {
        int rbase = wid * 16;
        if (row0 + rbase < N_NODES) {
            int c = lane * 3;
            float b0 = sB[c], b1 = sB[c + 1], b2 = sB[c + 2];
            int cur = sBatch[rbase];
            float a0 = 0.f, a1 = 0.f, a2 = 0.f;
            for (int rr = 0; rr < 16; rr++) {
                int r = rbase + rr;
                if (row0 + r >= N_NODES) break;
                int bg = sBatch[r];
                if (bg != cur) {
                    atomicAdd(&g_pool[cur * 96 + c + 0], a0);
                    atomicAdd(&g_pool[cur * 96 + c + 1], a1);
                    atomicAdd(&g_pool[cur * 96 + c + 2], a2);
                    a0 = a1 = a2 = 0.f;
                    cur = bg;
                }
                const float* p = &sC[r * 96 + c];
                a0 += fmaxf(p[0] + b0, 0.f);
                a1 += fmaxf(p[1] + b1, 0.f);
                a2 += fmaxf(p[2] + b2, 0.f);
            }
            atomicAdd(&g_pool[cur * 96 + c + 0], a0);
            atomicAdd(&g_pool[cur * 96 + c + 1], a1);
            atomicAdd(&g_pool[cur * 96 + c + 2], a2);
        }
    }
}

// ---------------- final MLP ------------------------------------------------
__global__ __launch_bounds__(128) void mlp_kernel(const float* __restrict__ Wf1,
                                                  const float* __restrict__ bf1,
                                                  const float* __restrict__ Wf2,
                                                  const float* __restrict__ bf2,
                                                  float* __restrict__ out) {
    int g = blockIdx.x * 4 + (threadIdx.x >> 5);
    int j = threadIdx.x & 31;
    if (g >= N_GRAPHS) return;
    float hj = bf1[j];
    const float* gp = &g_pool[g * HID];
#pragma unroll 8
    for (int i = 0; i < 96; i++) hj += gp[i] * Wf1[i * 32 + j];
    hj = fmaxf(hj, 0.f);
    float v = hj * Wf2[j];
#pragma unroll
    for (int off = 16; off; off >>= 1) v += __shfl_down_sync(0xffffffffu, v, off);
    if (j == 0) out[g] = v + bf2[0];
}

// ---------------- launch ---------------------------------------------------
extern "C" void kernel_launch(void* const* d_in, const int* in_sizes, int n_in,
                              void* d_out, int out_size) {
    const float* x     = (const float*)d_in[0];
    const int*   ei    = (const int*)d_in[1];
    const int*   batch = (const int*)d_in[2];
    const float* W1  = (const float*)d_in[3];
    const float* b1  = (const float*)d_in[4];
    const float* W2  = (const float*)d_in[5];
    const float* b2  = (const float*)d_in[6];
    const float* W3  = (const float*)d_in[7];
    const float* b3  = (const float*)d_in[8];
    const float* W4  = (const float*)d_in[9];
    const float* b4  = (const float*)d_in[10];
    const float* Wf1 = (const float*)d_in[11];
    const float* bf1 = (const float*)d_in[12];
    const float* Wf2 = (const float*)d_in[13];
    const float* bf2 = (const float*)d_in[14];
    float* out = (float*)d_out;

    __half *bufA, *bufB, *wh;
    cudaGetSymbolAddress((void**)&bufA, g_bufA);
    cudaGetSymbolAddress((void**)&bufB, g_bufB);
    cudaGetSymbolAddress((void**)&wh, g_wh);

    const int SM = 49152 + 384 + 512;   // 50048 B
    cudaFuncSetAttribute((const void*)gcn_layer<32, true,  false>, cudaFuncAttributeMaxDynamicSharedMemorySize, SM);
    cudaFuncSetAttribute((const void*)gcn_layer<96, true,  false>, cudaFuncAttributeMaxDynamicSharedMemorySize, SM);
    cudaFuncSetAttribute((const void*)gcn_layer<96, false, true >, cudaFuncAttributeMaxDynamicSharedMemorySize, SM);

    const int TB = 256;
    int nb_edges = (N_EDGES + TB - 1) / TB;

    // prep (zero deg/pool + W->fp16) and CSR build
    prep_kernel<<<NB, TB>>>(W1, W2, W3, W4);
    count_kernel<<<nb_edges, TB>>>(ei);
    scanA_kernel<<<NB, TB>>>();
    scanC_kernel<<<NB, TB>>>();
    fill_kernel<<<nb_edges, TB>>>(ei);

    scale0_kernel<<<(N_NODES * 8 + TB - 1) / TB, TB>>>(x, bufA);

    const int L_BLKS = (N_NODES + 127) / 128;   // 782

    gcn_layer<32, true,  false><<<L_BLKS, 256, SM>>>(bufA, bufB, wh,                    b1, batch);
    gcn_layer<96, true,  false><<<L_BLKS, 256, SM>>>(bufB, bufA, wh + 3072,             b2, batch);
    gcn_layer<96, true,  false><<<L_BLKS, 256, SM>>>(bufA, bufB, wh + 3072 + 9216,      b3, batch);
    gcn_layer<96, false, true ><<<L_BLKS, 256, SM>>>(bufB, bufA, wh + 3072 + 2 * 9216,  b4, batch);

    mlp_kernel<<<N_GRAPHS / 4, 128>>>(Wf1, bf1, Wf2, bf2, out);
}

// round 10
// speedup vs baseline: 2.1714x; 1.1829x over previous
#include <cuda_runtime.h>
#include <cuda_fp16.h>
#include <mma.h>
#include <cstdint>

using namespace nvcuda;

#define N_NODES  100000
#define N_EDGES  1600000
#define HID      96
#define N_GRAPHS 2048
#define NB       391        // ceil(N_NODES/256)

// ---------------- scratch (device globals; no allocation allowed) ----------
__device__ int    g_deg[N_NODES];
__device__ int    g_rowptr[N_NODES + 1];
__device__ int    g_tick[N_EDGES];
__device__ int    g_col[N_EDGES];
__device__ float  g_dinv[N_NODES];
__device__ __half g_bufA[N_NODES * HID];
__device__ __half g_bufB[N_NODES * HID];
__device__ float  g_pool[N_GRAPHS * HID];
__device__ __half g_wh[3072 + 3 * 9216];   // W1(32x96), W2..W4(96x96) fp16
__device__ int    g_bsum[NB];

// ---------------- half4 helpers --------------------------------------------
__device__ __forceinline__ float4 h4_to_f4(uint2 u) {
    __half2 a = *reinterpret_cast<__half2*>(&u.x);
    __half2 b = *reinterpret_cast<__half2*>(&u.y);
    float2 fa = __half22float2(a), fb = __half22float2(b);
    return make_float4(fa.x, fa.y, fb.x, fb.y);
}
__device__ __forceinline__ uint2 f4_to_h4(float4 v) {
    __half2 a = __floats2half2_rn(v.x, v.y);
    __half2 b = __floats2half2_rn(v.z, v.w);
    uint2 u;
    u.x = *reinterpret_cast<uint32_t*>(&a);
    u.y = *reinterpret_cast<uint32_t*>(&b);
    return u;
}

// ---------------- fused prep: zero deg, zero pool, W->fp16 ------------------
__global__ __launch_bounds__(256) void prep_kernel(const float* __restrict__ W1,
                                                   const float* __restrict__ W2,
                                                   const float* __restrict__ W3,
                                                   const float* __restrict__ W4) {
    int i = blockIdx.x * blockDim.x + threadIdx.x;
    if (i < N_NODES) g_deg[i] = 0;
    if (i < N_GRAPHS * HID / 4)
        ((float4*)g_pool)[i] = make_float4(0.f, 0.f, 0.f, 0.f);
    if (i < 3072)                 g_wh[i] = __float2half(W1[i]);
    else if (i < 3072 + 9216)     g_wh[i] = __float2half(W2[i - 3072]);
    else if (i < 3072 + 2 * 9216) g_wh[i] = __float2half(W3[i - 3072 - 9216]);
    else if (i < 3072 + 3 * 9216) g_wh[i] = __float2half(W4[i - 3072 - 2 * 9216]);
}

// ---------------- CSR build ------------------------------------------------
__global__ __launch_bounds__(256) void count_kernel(const int* __restrict__ ei) {
    int e = blockIdx.x * blockDim.x + threadIdx.x;
    if (e < N_EDGES) {
        int d = ei[N_EDGES + e];
        g_tick[e] = atomicAdd(&g_deg[d], 1);
    }
}

__global__ __launch_bounds__(256) void scanA_kernel() {
    __shared__ int sh[256];
    int t = threadIdx.x;
    int i = blockIdx.x * 256 + t;
    sh[t] = (i < N_NODES) ? g_deg[i] : 0;
    __syncthreads();
    for (int o = 128; o; o >>= 1) {
        if (t < o) sh[t] += sh[t + o];
        __syncthreads();
    }
    if (t == 0) g_bsum[blockIdx.x] = sh[0];
}

__global__ __launch_bounds__(256) void scanC_kernel() {
    __shared__ int sh[256];
    __shared__ int red[256];
    int t = threadIdx.x;
    int b = blockIdx.x;
    int i = b * 256 + t;
    int d = (i < N_NODES) ? g_deg[i] : 0;

    int part = 0;
    if (t < b)       part += g_bsum[t];
    if (t + 256 < b) part += g_bsum[t + 256];
    red[t] = part;
    __syncthreads();
    for (int o = 128; o; o >>= 1) {
        if (t < o) red[t] += red[t + o];
        __syncthreads();
    }
    int boff = red[0];

    sh[t] = d;
    __syncthreads();
    for (int o = 1; o < 256; o <<= 1) {
        int u = (t >= o) ? sh[t - o] : 0;
        __syncthreads();
        sh[t] += u;
        __syncthreads();
    }
    if (i < N_NODES) {
        g_rowptr[i] = boff + sh[t] - d;
        g_dinv[i]   = rsqrtf((float)(d + 1));
    }
    if (i == 0) g_rowptr[N_NODES] = N_EDGES;
}

__global__ __launch_bounds__(256) void fill_kernel(const int* __restrict__ ei) {
    int e = blockIdx.x * blockDim.x + threadIdx.x;
    if (e < N_EDGES) {
        int s = ei[e];
        int d = ei[N_EDGES + e];
        g_col[g_rowptr[d] + g_tick[e]] = s;
    }
}

// ---------------- xs0 = half(x * dinv) [N,32] -------------------------------
__global__ __launch_bounds__(256) void scale0_kernel(const float* __restrict__ x,
                                                     __half* __restrict__ out) {
    int idx = blockIdx.x * blockDim.x + threadIdx.x;
    if (idx < N_NODES * 8) {
        int node = idx >> 3;
        float d = g_dinv[node];
        float4 v = ((const float4*)x)[idx];
        v.x *= d; v.y *= d; v.z *= d; v.w *= d;
        ((uint2*)out)[idx] = f4_to_h4(v);
    }
}

// ---------------- fused layer: aggregate + wmma GEMM + epilogue -------------
// Block = 64 nodes, 256 threads (8 warps). Warp MMA tile 16x48 (1x3 frags).
// smem layout (bytes):
//   [0, 64*KP*2)                sA staging
//   [64*KP*2, +KD*104*2)        sW staging (padded stride 104 halves)
//   [0, 24576)                  sC overlay (64*96 fp32) -- after staging done
//   [33280, 33664)              sB bias (96 fp32)       -- beyond both overlays
//   [33664, 33920)              sBatch (64 ints)
template <int KD, bool SCALE_OUT, bool POOL>
__global__ __launch_bounds__(256, 4) void gcn_layer(const __half* __restrict__ Xin,
                                                    __half* __restrict__ Xout,
                                                    const __half* __restrict__ Wh,
                                                    const float* __restrict__ b,
                                                    const int* __restrict__ batch) {
    extern __shared__ __align__(16) char smem[];
    const int KP = KD + 8;                          // sA stride (halves)
    const int WP = 104;                             // sW stride (halves)
    __half* sA = (__half*)smem;                     // 64*KP halves
    __half* sW = (__half*)(smem + 64 * KP * 2);     // KD*WP halves
    float*  sC = (float*)smem;                      // overlay: 64*96 floats
    float*  sB = (float*)(smem + 33280);            // 96 floats
    int*    sBatch = (int*)(smem + 33664);          // 64 ints

    const int tid = threadIdx.x, wid = tid >> 5, lane = tid & 31;
    const int row0 = blockIdx.x * 64;

    // stage W (padded stride) + bias (+batch)
    for (int i = tid; i < KD * 12; i += 256) {
        int r = i / 12, c = i % 12;
        ((uint4*)(sW + r * WP))[c] = ((const uint4*)(Wh + r * 96))[c];
    }
    if (tid < 96) sB[tid] = b[tid];
    if (POOL)
        for (int i = tid; i < 64; i += 256)
            sBatch[i] = (row0 + i < N_NODES) ? batch[row0 + i] : -1;

    // ---- phase A: aggregation into sA ----
    const uint2* x2 = (const uint2*)Xin;
    if (KD == 96) {
        if (lane < 24) {
            const int f = lane;
            for (int rr = 0; rr < 8; rr++) {
                int r = wid * 8 + rr;
                int node = row0 + r;
                float4 acc = make_float4(0.f, 0.f, 0.f, 0.f);
                if (node < N_NODES) {
                    acc = h4_to_f4(x2[(long)node * 24 + f]);
                    int e0 = g_rowptr[node], e1 = g_rowptr[node + 1];
                    int e = e0;
                    for (; e + 8 <= e1; e += 8) {
                        int s[8];
#pragma unroll
                        for (int j = 0; j < 8; j++) s[j] = __ldg(&g_col[e + j]);
                        uint2 u[8];
#pragma unroll
                        for (int j = 0; j < 8; j++) u[j] = __ldg(&x2[(long)s[j] * 24 + f]);
#pragma unroll
                        for (int j = 0; j < 8; j++) {
                            float4 v = h4_to_f4(u[j]);
                            acc.x += v.x; acc.y += v.y; acc.z += v.z; acc.w += v.w;
                        }
                    }
                    for (; e < e1; e++) {
                        int s = __ldg(&g_col[e]);
                        float4 v = h4_to_f4(__ldg(&x2[(long)s * 24 + f]));
                        acc.x += v.x; acc.y += v.y; acc.z += v.z; acc.w += v.w;
                    }
                    float d = g_dinv[node];
                    acc.x *= d; acc.y *= d; acc.z *= d; acc.w *= d;
                }
                *(uint2*)&sA[r * KP + f * 4] = f4_to_h4(acc);
            }
        }
    } else {  // KD == 32: 4 nodes per warp in parallel, 8 lanes each
        const int f = lane & 7, sub = lane >> 3;
        for (int g4 = 0; g4 < 2; g4++) {
            int r = wid * 8 + g4 * 4 + sub;
            int node = row0 + r;
            float4 acc = make_float4(0.f, 0.f, 0.f, 0.f);
            if (node < N_NODES) {
                acc = h4_to_f4(x2[(long)node * 8 + f]);
                int e0 = g_rowptr[node], e1 = g_rowptr[node + 1];
                int e = e0;
                for (; e + 4 <= e1; e += 4) {
                    int s[4];
#pragma unroll
                    for (int j = 0; j < 4; j++) s[j] = __ldg(&g_col[e + j]);
                    uint2 u[4];
#pragma unroll
                    for (int j = 0; j < 4; j++) u[j] = __ldg(&x2[(long)s[j] * 8 + f]);
#pragma unroll
                    for (int j = 0; j < 4; j++) {
                        float4 v = h4_to_f4(u[j]);
                        acc.x += v.x; acc.y += v.y; acc.z += v.z; acc.w += v.w;
                    }
                }
                for (; e < e1; e++) {
                    int s = __ldg(&g_col[e]);
                    float4 v = h4_to_f4(__ldg(&x2[(long)s * 8 + f]));
                    acc.x += v.x; acc.y += v.y; acc.z += v.z; acc.w += v.w;
                }
                float d = g_dinv[node];
                acc.x *= d; acc.y *= d; acc.z *= d; acc.w *= d;
            }
            *(uint2*)&sA[r * KP + f * 4] = f4_to_h4(acc);
        }
    }
    __syncthreads();

    // ---- phase B: wmma, warp tile 16x48 ----
    const int wm = (wid >> 1) * 16;
    const int wn = (wid & 1) * 48;

    wmma::fragment<wmma::accumulator, 16, 16, 16, float> acc[3];
#pragma unroll
    for (int j = 0; j < 3; j++) wmma::fill_fragment(acc[j], 0.f);

#pragma unroll
    for (int k0 = 0; k0 < KD; k0 += 16) {
        wmma::fragment<wmma::matrix_a, 16, 16, 16, __half, wmma::row_major> af;
        wmma::fragment<wmma::matrix_b, 16, 16, 16, __half, wmma::row_major> bf[3];
        wmma::load_matrix_sync(af, &sA[wm * KP + k0], KP);
#pragma unroll
        for (int j = 0; j < 3; j++)
            wmma::load_matrix_sync(bf[j], &sW[k0 * WP + wn + j * 16], WP);
#pragma unroll
        for (int j = 0; j < 3; j++)
            wmma::mma_sync(acc[j], af, bf[j], acc[j]);
    }

    __syncthreads();   // reuse smem as sC
#pragma unroll
    for (int j = 0; j < 3; j++)
        wmma::store_matrix_sync(&sC[wm * 96 + wn + j * 16], acc[j], 96,
                                wmma::mem_row_major);
    __syncthreads();

    // ---- phase C: epilogue ----
    if (!POOL) {
        for (int i = tid; i < 64 * 24; i += 256) {
            int r = i / 24, c2 = i % 24;
            int row = row0 + r;
            if (row >= N_NODES) continue;
            float d = SCALE_OUT ? g_dinv[row] : 1.f;
            const float* p = &sC[r * 96 + c2 * 4];
            float4 v;
            int c = c2 * 4;
            v.x = fmaxf(p[0] + sB[c + 0], 0.f) * d;
            v.y = fmaxf(p[1] + sB[c + 1], 0.f) * d;
            v.z = fmaxf(p[2] + sB[c + 2], 0.f) * d;
            v.w = fmaxf(p[3] + sB[c + 3], 0.f) * d;
            ((uint2*)&Xout[(long)row * 96])[c2] = f4_to_h4(v);
        }
    } else {
        int rbase = wid * 8;
        if (row0 + rbase < N_NODES) {
            int c = lane * 3;
            float b0 = sB[c], b1 = sB[c + 1], b2 = sB[c + 2];
            int cur = sBatch[rbase];
            float a0 = 0.f, a1 = 0.f, a2 = 0.f;
            for (int rr = 0; rr < 8; rr++) {
                int r = rbase + rr;
                if (row0 + r >= N_NODES) break;
                int bg = sBatch[r];
                if (bg != cur) {
                    atomicAdd(&g_pool[cur * 96 + c + 0], a0);
                    atomicAdd(&g_pool[cur * 96 + c + 1], a1);
                    atomicAdd(&g_pool[cur * 96 + c + 2], a2);
                    a0 = a1 = a2 = 0.f;
                    cur = bg;
                }
                const float* p = &sC[r * 96 + c];
                a0 += fmaxf(p[0] + b0, 0.f);
                a1 += fmaxf(p[1] + b1, 0.f);
                a2 += fmaxf(p[2] + b2, 0.f);
            }
            atomicAdd(&g_pool[cur * 96 + c + 0], a0);
            atomicAdd(&g_pool[cur * 96 + c + 1], a1);
            atomicAdd(&g_pool[cur * 96 + c + 2], a2);
        }
    }
}

// ---------------- final MLP ------------------------------------------------
__global__ __launch_bounds__(128) void mlp_kernel(const float* __restrict__ Wf1,
                                                  const float* __restrict__ bf1,
                                                  const float* __restrict__ Wf2,
                                                  const float* __restrict__ bf2,
                                                  float* __restrict__ out) {
    int g = blockIdx.x * 4 + (threadIdx.x >> 5);
    int j = threadIdx.x & 31;
    if (g >= N_GRAPHS) return;
    float hj = bf1[j];
    const float* gp = &g_pool[g * HID];
#pragma unroll 8
    for (int i = 0; i < 96; i++) hj += gp[i] * Wf1[i * 32 + j];
    hj = fmaxf(hj, 0.f);
    float v = hj * Wf2[j];
#pragma unroll
    for (int off = 16; off; off >>= 1) v += __shfl_down_sync(0xffffffffu, v, off);
    if (j == 0) out[g] = v + bf2[0];
}

// ---------------- launch ---------------------------------------------------
extern "C" void kernel_launch(void* const* d_in, const int* in_sizes, int n_in,
                              void* d_out, int out_size) {
    const float* x     = (const float*)d_in[0];
    const int*   ei    = (const int*)d_in[1];
    const int*   batch = (const int*)d_in[2];
    const float* W1  = (const float*)d_in[3];
    const float* b1  = (const float*)d_in[4];
    const float* W2  = (const float*)d_in[5];
    const float* b2  = (const float*)d_in[6];
    const float* W3  = (const float*)d_in[7];
    const float* b3  = (const float*)d_in[8];
    const float* W4  = (const float*)d_in[9];
    const float* b4  = (const float*)d_in[10];
    const float* Wf1 = (const float*)d_in[11];
    const float* bf1 = (const float*)d_in[12];
    const float* Wf2 = (const float*)d_in[13];
    const float* bf2 = (const float*)d_in[14];
    float* out = (float*)d_out;

    __half *bufA, *bufB, *wh;
    cudaGetSymbolAddress((void**)&bufA, g_bufA);
    cudaGetSymbolAddress((void**)&bufB, g_bufB);
    cudaGetSymbolAddress((void**)&wh, g_wh);

    // smem: staging ends at 33280 (KD=96); sB 33280..33664; sBatch 33664..33920
    const int SM2 = 33920;
    cudaFuncSetAttribute((const void*)gcn_layer<32, true,  false>, cudaFuncAttributeMaxDynamicSharedMemorySize, SM2);
    cudaFuncSetAttribute((const void*)gcn_layer<96, true,  false>, cudaFuncAttributeMaxDynamicSharedMemorySize, SM2);
    cudaFuncSetAttribute((const void*)gcn_layer<96, false, true >, cudaFuncAttributeMaxDynamicSharedMemorySize, SM2);

    const int TB = 256;
    int nb_edges = (N_EDGES + TB - 1) / TB;

    prep_kernel<<<NB, TB>>>(W1, W2, W3, W4);
    count_kernel<<<nb_edges, TB>>>(ei);
    scanA_kernel<<<NB, TB>>>();
    scanC_kernel<<<NB, TB>>>();
    fill_kernel<<<nb_edges, TB>>>(ei);

    scale0_kernel<<<(N_NODES * 8 + TB - 1) / TB, TB>>>(x, bufA);

    const int L_BLKS = (N_NODES + 63) / 64;   // 1563

    gcn_layer<32, true,  false><<<L_BLKS, 256, SM2>>>(bufA, bufB, wh,                    b1, batch);
    gcn_layer<96, true,  false><<<L_BLKS, 256, SM2>>>(bufB, bufA, wh + 3072,             b2, batch);
    gcn_layer<96, true,  false><<<L_BLKS, 256, SM2>>>(bufA, bufB, wh + 3072 + 9216,      b3, batch);
    gcn_layer<96, false, true ><<<L_BLKS, 256, SM2>>>(bufB, bufA, wh + 3072 + 2 * 9216,  b4, batch);

    mlp_kernel<<<N_GRAPHS / 4, 128>>>(Wf1, bf1, Wf2, bf2, out);
}

// round 12
// speedup vs baseline: 2.3777x; 1.0950x over previous
#include <cuda_runtime.h>
#include <cuda_fp16.h>
#include <mma.h>
#include <cstdint>

using namespace nvcuda;

#define N_NODES  100000
#define N_EDGES  1600000
#define HID      96
#define N_GRAPHS 2048
#define NB       391        // ceil(N_NODES/256)

// ---------------- scratch (device globals; no allocation allowed) ----------
__device__ int    g_deg[N_NODES];
__device__ int    g_rowptr[N_NODES + 1];
__device__ int    g_tick[N_EDGES];
__device__ int    g_col[N_EDGES];
__device__ float  g_dinv[N_NODES];
__device__ __half g_bufA[N_NODES * HID];
__device__ __half g_bufB[N_NODES * HID];
__device__ float  g_pool[N_GRAPHS * HID];
__device__ __half g_wh[3072 + 3 * 9216];   // W1(32x96), W2..W4(96x96) fp16
__device__ int    g_bsum[NB];

// ---------------- helpers ---------------------------------------------------
__device__ __forceinline__ float4 h4_to_f4(uint2 u) {
    __half2 a = *reinterpret_cast<__half2*>(&u.x);
    __half2 b = *reinterpret_cast<__half2*>(&u.y);
    float2 fa = __half22float2(a), fb = __half22float2(b);
    return make_float4(fa.x, fa.y, fb.x, fb.y);
}
__device__ __forceinline__ uint2 f4_to_h4(float4 v) {
    __half2 a = __floats2half2_rn(v.x, v.y);
    __half2 b = __floats2half2_rn(v.z, v.w);
    uint2 u;
    u.x = *reinterpret_cast<uint32_t*>(&a);
    u.y = *reinterpret_cast<uint32_t*>(&b);
    return u;
}
__device__ __forceinline__ void acc_u4(float4& a0, float4& a1, uint4 u) {
    float4 v0 = h4_to_f4(make_uint2(u.x, u.y));
    float4 v1 = h4_to_f4(make_uint2(u.z, u.w));
    a0.x += v0.x; a0.y += v0.y; a0.z += v0.z; a0.w += v0.w;
    a1.x += v1.x; a1.y += v1.y; a1.z += v1.z; a1.w += v1.w;
}

// ---------------- fused prep: zero deg, zero pool, W->fp16 ------------------
__global__ __launch_bounds__(256) void prep_kernel(const float* __restrict__ W1,
                                                   const float* __restrict__ W2,
                                                   const float* __restrict__ W3,
                                                   const float* __restrict__ W4) {
    int i = blockIdx.x * blockDim.x + threadIdx.x;
    if (i < N_NODES) g_deg[i] = 0;
    if (i < N_GRAPHS * HID / 4)
        ((float4*)g_pool)[i] = make_float4(0.f, 0.f, 0.f, 0.f);
    if (i < 3072)                 g_wh[i] = __float2half(W1[i]);
    else if (i < 3072 + 9216)     g_wh[i] = __float2half(W2[i - 3072]);
    else if (i < 3072 + 2 * 9216) g_wh[i] = __float2half(W3[i - 3072 - 9216]);
    else if (i < 3072 + 3 * 9216) g_wh[i] = __float2half(W4[i - 3072 - 2 * 9216]);
}

// ---------------- CSR build (4 edges / thread) ------------------------------
__global__ __launch_bounds__(256) void count_kernel(const int* __restrict__ ei) {
    int t = blockIdx.x * blockDim.x + threadIdx.x;
    if (t < N_EDGES / 4) {
        int4 d4 = __ldg(&((const int4*)(ei + N_EDGES))[t]);
        int4 tk;
        tk.x = atomicAdd(&g_deg[d4.x], 1);
        tk.y = atomicAdd(&g_deg[d4.y], 1);
        tk.z = atomicAdd(&g_deg[d4.z], 1);
        tk.w = atomicAdd(&g_deg[d4.w], 1);
        ((int4*)g_tick)[t] = tk;
    }
}

__global__ __launch_bounds__(256) void scanA_kernel() {
    __shared__ int sh[256];
    int t = threadIdx.x;
    int i = blockIdx.x * 256 + t;
    sh[t] = (i < N_NODES) ? g_deg[i] : 0;
    __syncthreads();
    for (int o = 128; o; o >>= 1) {
        if (t < o) sh[t] += sh[t + o];
        __syncthreads();
    }
    if (t == 0) g_bsum[blockIdx.x] = sh[0];
}

__global__ __launch_bounds__(256) void scanC_kernel() {
    __shared__ int sh[256];
    __shared__ int red[256];
    int t = threadIdx.x;
    int b = blockIdx.x;
    int i = b * 256 + t;
    int d = (i < N_NODES) ? g_deg[i] : 0;

    int part = 0;
    if (t < b)       part += g_bsum[t];
    if (t + 256 < b) part += g_bsum[t + 256];
    red[t] = part;
    __syncthreads();
    for (int o = 128; o; o >>= 1) {
        if (t < o) red[t] += red[t + o];
        __syncthreads();
    }
    int boff = red[0];

    sh[t] = d;
    __syncthreads();
    for (int o = 1; o < 256; o <<= 1) {
        int u = (t >= o) ? sh[t - o] : 0;
        __syncthreads();
        sh[t] += u;
        __syncthreads();
    }
    if (i < N_NODES) {
        g_rowptr[i] = boff + sh[t] - d;
        g_dinv[i]   = rsqrtf((float)(d + 1));
    }
    if (i == 0) g_rowptr[N_NODES] = N_EDGES;
}

__global__ __launch_bounds__(256) void fill_kernel(const int* __restrict__ ei) {
    int t = blockIdx.x * blockDim.x + threadIdx.x;
    if (t < N_EDGES / 4) {
        int4 s4 = __ldg(&((const int4*)ei)[t]);
        int4 d4 = __ldg(&((const int4*)(ei + N_EDGES))[t]);
        int4 tk = __ldg(&((const int4*)g_tick)[t]);
        g_col[g_rowptr[d4.x] + tk.x] = s4.x;
        g_col[g_rowptr[d4.y] + tk.y] = s4.y;
        g_col[g_rowptr[d4.z] + tk.z] = s4.z;
        g_col[g_rowptr[d4.w] + tk.w] = s4.w;
    }
}

// ---------------- xs0 = half(x * dinv) [N,32] -------------------------------
__global__ __launch_bounds__(256) void scale0_kernel(const float* __restrict__ x,
                                                     __half* __restrict__ out) {
    int idx = blockIdx.x * blockDim.x + threadIdx.x;
    if (idx < N_NODES * 8) {
        int node = idx >> 3;
        float d = g_dinv[node];
        float4 v = ((const float4*)x)[idx];
        v.x *= d; v.y *= d; v.z *= d; v.w *= d;
        ((uint2*)out)[idx] = f4_to_h4(v);
    }
}

// ---------------- fused layer: aggregate + wmma GEMM + epilogue -------------
// Block = 64 nodes, 256 threads (8 warps). Warp MMA tile 16x48 (1x3 frags).
// Gather uses 16B lanes: KD=96 -> 12 lanes/row, 2 nodes concurrent per warp;
// KD=32 -> 4 lanes/row (4 uint4 per 32-half row), 8 nodes concurrent.
// smem (bytes): sA [0,64*KP*2) | sW [64*KP*2, +KD*104*2) | sC overlay [0,24576)
//               sB @33280 | sBatch @33664
template <int KD, bool SCALE_OUT, bool POOL>
__global__ __launch_bounds__(256, 4) void gcn_layer(const __half* __restrict__ Xin,
                                                    __half* __restrict__ Xout,
                                                    const __half* __restrict__ Wh,
                                                    const float* __restrict__ b,
                                                    const int* __restrict__ batch) {
    extern __shared__ __align__(16) char smem[];
    const int KP = KD + 8;                          // sA stride (halves)
    const int WP = 104;                             // sW stride (halves)
    __half* sA = (__half*)smem;
    __half* sW = (__half*)(smem + 64 * KP * 2);
    float*  sC = (float*)smem;
    float*  sB = (float*)(smem + 33280);
    int*    sBatch = (int*)(smem + 33664);

    const int tid = threadIdx.x, wid = tid >> 5, lane = tid & 31;
    const int row0 = blockIdx.x * 64;

    for (int i = tid; i < KD * 12; i += 256) {
        int r = i / 12, c = i % 12;
        ((uint4*)(sW + r * WP))[c] = ((const uint4*)(Wh + r * 96))[c];
    }
    if (tid < 96) sB[tid] = b[tid];
    if (POOL)
        for (int i = tid; i < 64; i += 256)
            sBatch[i] = (row0 + i < N_NODES) ? batch[row0 + i] : -1;

    // ---- phase A: aggregation into sA (16B lanes) ----
    const uint4* x4 = (const uint4*)Xin;
    if (KD == 96) {
        if (lane < 24) {
            const int q = lane % 12;       // uint4 index within row (12 per row)
            const int sub = lane / 12;     // 0..1 : concurrent node
#pragma unroll
            for (int rr = 0; rr < 4; rr++) {
                int r = wid * 8 + rr * 2 + sub;
                int node = row0 + r;
                float4 a0 = make_float4(0.f, 0.f, 0.f, 0.f);
                float4 a1 = make_float4(0.f, 0.f, 0.f, 0.f);
                if (node < N_NODES) {
                    acc_u4(a0, a1, __ldg(&x4[(long)node * 12 + q]));  // self
                    int e0 = g_rowptr[node], e1 = g_rowptr[node + 1];
                    int e = e0;
                    for (; e + 4 <= e1; e += 4) {
                        int s0 = __ldg(&g_col[e + 0]);
                        int s1 = __ldg(&g_col[e + 1]);
                        int s2 = __ldg(&g_col[e + 2]);
                        int s3 = __ldg(&g_col[e + 3]);
                        uint4 u0 = __ldg(&x4[(long)s0 * 12 + q]);
                        uint4 u1 = __ldg(&x4[(long)s1 * 12 + q]);
                        uint4 u2 = __ldg(&x4[(long)s2 * 12 + q]);
                        uint4 u3 = __ldg(&x4[(long)s3 * 12 + q]);
                        acc_u4(a0, a1, u0); acc_u4(a0, a1, u1);
                        acc_u4(a0, a1, u2); acc_u4(a0, a1, u3);
                    }
                    for (; e < e1; e++) {
                        int s = __ldg(&g_col[e]);
                        acc_u4(a0, a1, __ldg(&x4[(long)s * 12 + q]));
                    }
                    float d = g_dinv[node];
                    a0.x *= d; a0.y *= d; a0.z *= d; a0.w *= d;
                    a1.x *= d; a1.y *= d; a1.z *= d; a1.w *= d;
                }
                uint2 lo = f4_to_h4(a0), hi = f4_to_h4(a1);
                *(uint4*)&sA[r * KP + q * 8] = make_uint4(lo.x, lo.y, hi.x, hi.y);
            }
        }
    } else {  // KD == 32: 4 uint4 per row (32 halves), 8 rows concurrent, all 32 lanes
        const int q = lane & 3;        // uint4 index within row (4 per row)
        const int sub = lane >> 2;     // 0..7 : node within warp's 8 rows
        int r = wid * 8 + sub;
        int node = row0 + r;
        float4 a0 = make_float4(0.f, 0.f, 0.f, 0.f);
        float4 a1 = make_float4(0.f, 0.f, 0.f, 0.f);
        if (node < N_NODES) {
            acc_u4(a0, a1, __ldg(&x4[(long)node * 4 + q]));  // self
            int e0 = g_rowptr[node], e1 = g_rowptr[node + 1];
            int e = e0;
            for (; e + 4 <= e1; e += 4) {
                int s0 = __ldg(&g_col[e + 0]);
                int s1 = __ldg(&g_col[e + 1]);
                int s2 = __ldg(&g_col[e + 2]);
                int s3 = __ldg(&g_col[e + 3]);
                uint4 u0 = __ldg(&x4[(long)s0 * 4 + q]);
                uint4 u1 = __ldg(&x4[(long)s1 * 4 + q]);
                uint4 u2 = __ldg(&x4[(long)s2 * 4 + q]);
                uint4 u3 = __ldg(&x4[(long)s3 * 4 + q]);
                acc_u4(a0, a1, u0); acc_u4(a0, a1, u1);
                acc_u4(a0, a1, u2); acc_u4(a0, a1, u3);
            }
            for (; e < e1; e++) {
                int s = __ldg(&g_col[e]);
                acc_u4(a0, a1, __ldg(&x4[(long)s * 4 + q]));
            }
            float d = g_dinv[node];
            a0.x *= d; a0.y *= d; a0.z *= d; a0.w *= d;
            a1.x *= d; a1.y *= d; a1.z *= d; a1.w *= d;
        }
        uint2 lo = f4_to_h4(a0), hi = f4_to_h4(a1);
        *(uint4*)&sA[r * KP + q * 8] = make_uint4(lo.x, lo.y, hi.x, hi.y);
    }
    __syncthreads();

    // ---- phase B: wmma, warp tile 16x48 ----
    const int wm = (wid >> 1) * 16;
    const int wn = (wid & 1) * 48;

    wmma::fragment<wmma::accumulator, 16, 16, 16, float> acc[3];
#pragma unroll
    for (int j = 0; j < 3; j++) wmma::fill_fragment(acc[j], 0.f);

#pragma unroll
    for (int k0 = 0; k0 < KD; k0 += 16) {
        wmma::fragment<wmma::matrix_a, 16, 16, 16, __half, wmma::row_major> af;
        wmma::fragment<wmma::matrix_b, 16, 16, 16, __half, wmma::row_major> bf[3];
        wmma::load_matrix_sync(af, &sA[wm * KP + k0], KP);
#pragma unroll
        for (int j = 0; j < 3; j++)
            wmma::load_matrix_sync(bf[j], &sW[k0 * WP + wn + j * 16], WP);
#pragma unroll
        for (int j = 0; j < 3; j++)
            wmma::mma_sync(acc[j], af, bf[j], acc[j]);
    }

    __syncthreads();
#pragma unroll
    for (int j = 0; j < 3; j++)
        wmma::store_matrix_sync(&sC[wm * 96 + wn + j * 16], acc[j], 96,
                                wmma::mem_row_major);
    __syncthreads();

    // ---- phase C: epilogue ----
    if (!POOL) {
        for (int i = tid; i < 64 * 24; i += 256) {
            int r = i / 24, c2 = i % 24;
            int row = row0 + r;
            if (row >= N_NODES) continue;
            float d = SCALE_OUT ? g_dinv[row] : 1.f;
            const float* p = &sC[r * 96 + c2 * 4];
            float4 v;
            int c = c2 * 4;
            v.x = fmaxf(p[0] + sB[c + 0], 0.f) * d;
            v.y = fmaxf(p[1] + sB[c + 1], 0.f) * d;
            v.z = fmaxf(p[2] + sB[c + 2], 0.f) * d;
            v.w = fmaxf(p[3] + sB[c + 3], 0.f) * d;
            ((uint2*)&Xout[(long)row * 96])[c2] = f4_to_h4(v);
        }
    } else {
        int rbase = wid * 8;
        if (row0 + rbase < N_NODES) {
            int c = lane * 3;
            float b0 = sB[c], b1 = sB[c + 1], b2 = sB[c + 2];
            int cur = sBatch[rbase];
            float a0 = 0.f, a1 = 0.f, a2 = 0.f;
            for (int rr = 0; rr < 8; rr++) {
                int r = rbase + rr;
                if (row0 + r >= N_NODES) break;
                int bg = sBatch[r];
                if (bg != cur) {
                    atomicAdd(&g_pool[cur * 96 + c + 0], a0);
                    atomicAdd(&g_pool[cur * 96 + c + 1], a1);
                    atomicAdd(&g_pool[cur * 96 + c + 2], a2);
                    a0 = a1 = a2 = 0.f;
                    cur = bg;
                }
                const float* p = &sC[r * 96 + c];
                a0 += fmaxf(p[0] + b0, 0.f);
                a1 += fmaxf(p[1] + b1, 0.f);
                a2 += fmaxf(p[2] + b2, 0.f);
            }
            atomicAdd(&g_pool[cur * 96 + c + 0], a0);
            atomicAdd(&g_pool[cur * 96 + c + 1], a1);
            atomicAdd(&g_pool[cur * 96 + c + 2], a2);
        }
    }
}

// ---------------- final MLP ------------------------------------------------
__global__ __launch_bounds__(128) void mlp_kernel(const float* __restrict__ Wf1,
                                                  const float* __restrict__ bf1,
                                                  const float* __restrict__ Wf2,
                                                  const float* __restrict__ bf2,
                                                  float* __restrict__ out) {
    int g = blockIdx.x * 4 + (threadIdx.x >> 5);
    int j = threadIdx.x & 31;
    if (g >= N_GRAPHS) return;
    float hj = bf1[j];
    const float* gp = &g_pool[g * HID];
#pragma unroll 8
    for (int i = 0; i < 96; i++) hj += gp[i] * Wf1[i * 32 + j];
    hj = fmaxf(hj, 0.f);
    float v = hj * Wf2[j];
#pragma unroll
    for (int off = 16; off; off >>= 1) v += __shfl_down_sync(0xffffffffu, v, off);
    if (j == 0) out[g] = v + bf2[0];
}

// ---------------- launch ---------------------------------------------------
extern "C" void kernel_launch(void* const* d_in, const int* in_sizes, int n_in,
                              void* d_out, int out_size) {
    const float* x     = (const float*)d_in[0];
    const int*   ei    = (const int*)d_in[1];
    const int*   batch = (const int*)d_in[2];
    const float* W1  = (const float*)d_in[3];
    const float* b1  = (const float*)d_in[4];
    const float* W2  = (const float*)d_in[5];
    const float* b2  = (const float*)d_in[6];
    const float* W3  = (const float*)d_in[7];
    const float* b3  = (const float*)d_in[8];
    const float* W4  = (const float*)d_in[9];
    const float* b4  = (const float*)d_in[10];
    const float* Wf1 = (const float*)d_in[11];
    const float* bf1 = (const float*)d_in[12];
    const float* Wf2 = (const float*)d_in[13];
    const float* bf2 = (const float*)d_in[14];
    float* out = (float*)d_out;

    __half *bufA, *bufB, *wh;
    cudaGetSymbolAddress((void**)&bufA, g_bufA);
    cudaGetSymbolAddress((void**)&bufB, g_bufB);
    cudaGetSymbolAddress((void**)&wh, g_wh);

    const int SM2 = 33920;
    cudaFuncSetAttribute((const void*)gcn_layer<32, true,  false>, cudaFuncAttributeMaxDynamicSharedMemorySize, SM2);
    cudaFuncSetAttribute((const void*)gcn_layer<96, true,  false>, cudaFuncAttributeMaxDynamicSharedMemorySize, SM2);
    cudaFuncSetAttribute((const void*)gcn_layer<96, false, true >, cudaFuncAttributeMaxDynamicSharedMemorySize, SM2);

    const int TB = 256;
    int nb_e4 = (N_EDGES / 4 + TB - 1) / TB;   // 1563

    prep_kernel<<<NB, TB>>>(W1, W2, W3, W4);
    count_kernel<<<nb_e4, TB>>>(ei);
    scanA_kernel<<<NB, TB>>>();
    scanC_kernel<<<NB, TB>>>();
    fill_kernel<<<nb_e4, TB>>>(ei);

    scale0_kernel<<<(N_NODES * 8 + TB - 1) / TB, TB>>>(x, bufA);

    const int L_BLKS = (N_NODES + 63) / 64;   // 1563

    gcn_layer<32, true,  false><<<L_BLKS, 256, SM2>>>(bufA, bufB, wh,                    b1, batch);
    gcn_layer<96, true,  false><<<L_BLKS, 256, SM2>>>(bufB, bufA, wh + 3072,             b2, batch);
    gcn_layer<96, true,  false><<<L_BLKS, 256, SM2>>>(bufA, bufB, wh + 3072 + 9216,      b3, batch);
    gcn_layer<96, false, true ><<<L_BLKS, 256, SM2>>>(bufB, bufA, wh + 3072 + 2 * 9216,  b4, batch);

    mlp_kernel<<<N_GRAPHS / 4, 128>>>(Wf1, bf1, Wf2, bf2, out);
}